// round 12
// baseline (speedup 1.0000x reference)
#include <cuda_runtime.h>
#include <cuda_fp16.h>
#include <cstdint>

#define BB 64
#define TT 1500
#define FF 36
#define HH 512
#define NT 256          // 8 warps: ks2 x mt4
#define GRID 128        // 64 CTAs per layer, 8 units per CTA

// ---------------- device globals ----------------
__device__ uint32_t g_xg0ph[(size_t)TT * 65536];  // 393MB fp16 acc-init [t][c64][tl128][16h]
__device__ float g_b2p[64 * 2048];                // layer2 bias  [c][tl128][q4][e4]
__device__ uint32_t g_wf1[64 * 8192];             // layer1 B-frags [c][kt32][p2][lane32][e4]
__device__ uint32_t g_wf2[64 * 16384];            // layer2 B-frags [c][kt64][p2][lane32][e4]
__device__ uint32_t g_h1s[4 * 16384];             // h1 ring, fp16 A-frag layout
__device__ uint32_t g_h2s[2 * 16384];             // h2 ring
// 4 group counters per (layer, step): group g = producer CTAs [16g,16g+16); target 128 (16 CTAs x 8 warps)
struct alignas(128) FlagG { unsigned g[4]; unsigned pad[28]; };
__device__ FlagG g_f1[TT + 2];
__device__ FlagG g_f2[TT + 2];

// ---------------- helpers ----------------
__device__ __forceinline__ float tanha(float x) {
    float y;
    asm("tanh.approx.f32 %0, %1;" : "=f"(y) : "f"(x));
    return y;
}
__device__ __forceinline__ float sigm(float x) { return fmaf(tanha(0.5f * x), 0.5f, 0.5f); }

__device__ __forceinline__ uint32_t f2h2(float lo, float hi) {
    __half2 h = __floats2half2_rn(lo, hi);
    return *reinterpret_cast<uint32_t*>(&h);
}

__device__ __forceinline__ void mma16(float* d, uint4 a, uint32_t b0, uint32_t b1) {
    asm volatile(
        "mma.sync.aligned.m16n8k16.row.col.f32.f16.f16.f32 "
        "{%0,%1,%2,%3},{%4,%5,%6,%7},{%8,%9},{%0,%1,%2,%3};\n"
        : "+f"(d[0]), "+f"(d[1]), "+f"(d[2]), "+f"(d[3])
        : "r"(a.x), "r"(a.y), "r"(a.z), "r"(a.w), "r"(b0), "r"(b1));
}

__device__ __forceinline__ void waitflag(const unsigned* p, unsigned tgt) {
    unsigned v;
    do {
        asm volatile("ld.acquire.gpu.global.u32 %0, [%1];" : "=r"(v) : "l"(p) : "memory");
    } while (v < tgt);
}
__device__ __forceinline__ void waitflag4(const FlagG* f, unsigned tgt) {
    unsigned a, b, c, d;
    do {
        asm volatile("ld.acquire.gpu.global.u32 %0, [%1];" : "=r"(a) : "l"(&f->g[0]) : "memory");
        asm volatile("ld.acquire.gpu.global.u32 %0, [%1];" : "=r"(b) : "l"(&f->g[1]) : "memory");
        asm volatile("ld.acquire.gpu.global.u32 %0, [%1];" : "=r"(c) : "l"(&f->g[2]) : "memory");
        asm volatile("ld.acquire.gpu.global.u32 %0, [%1];" : "=r"(d) : "l"(&f->g[3]) : "memory");
    } while (a < tgt || b < tgt || c < tgt || d < tgt);
}

// 8 k16-tiles: per kt: 1 LDG.128 (A) + 2 LDS.128 (B) + 4 MMA.
__device__ __forceinline__ void gemm8(float acc[4][4], const uint4* __restrict__ Ap,
                                      const uint4* __restrict__ Bp) {
    uint4 aq[8];
#pragma unroll
    for (int i = 0; i < 8; i++) aq[i] = __ldcg(Ap + i * 128);
#pragma unroll
    for (int i = 0; i < 8; i++) {
        uint4 av = aq[i];
        uint4 q1 = Bp[i * 64];
        uint4 q2 = Bp[i * 64 + 32];
        mma16(acc[0], av, q1.x, q1.y);
        mma16(acc[1], av, q1.z, q1.w);
        mma16(acc[2], av, q2.x, q2.y);
        mma16(acc[3], av, q2.z, q2.w);
    }
}

// ---------------- setup kernels ----------------
__global__ void reset_kernel() {
    int idx = blockIdx.x * 256 + threadIdx.x;
    if (idx < TT + 2) {
#pragma unroll
        for (int j = 0; j < 4; j++) {
            g_f1[idx].g[j] = (idx == 0) ? 128u : 0u;
            g_f2[idx].g[j] = (idx == 0) ? 128u : 0u;
        }
    }
    if (idx < 16384) {
        g_h1s[3 * 16384 + idx] = 0u;   // h1[-1] slab ((-1)&3 = 3)
        g_h2s[16384 + idx] = 0u;       // h2[-1] slab ((-1)&1 = 1)
    }
}

__global__ void pack_kernel(const float* __restrict__ Whh0, const float* __restrict__ Wih1,
                            const float* __restrict__ Whh1, const float* __restrict__ bih1,
                            const float* __restrict__ bhh1) {
    int cb = blockIdx.x;
    if (cb < 64) {
        int c = cb;
        uint32_t* dst = g_wf1 + c * 8192;
        for (int idx = threadIdx.x; idx < 8192; idx += 256) {
            int e = idx & 3, lane = (idx >> 2) & 31, p = (idx >> 7) & 1, kt = idx >> 8;
            int gid = lane >> 2, tig = lane & 3;
            int nt = 2 * p + (e >> 1);
            int gate = (nt & 1) * 2 + (gid & 1);
            int u = c * 8 + (nt >> 1) * 4 + (gid >> 1);
            int row = gate * 512 + u;
            int k = kt * 16 + (e & 1) * 8 + tig * 2;
            dst[idx] = f2h2(Whh0[row * HH + k], Whh0[row * HH + k + 1]);
        }
    } else {
        int c = cb - 64;
        uint32_t* dst = g_wf2 + c * 16384;
        for (int idx = threadIdx.x; idx < 16384; idx += 256) {
            int e = idx & 3, lane = (idx >> 2) & 31, p = (idx >> 7) & 1, kt = idx >> 8;
            int gid = lane >> 2, tig = lane & 3;
            int nt = 2 * p + (e >> 1);
            int gate = (nt & 1) * 2 + (gid & 1);
            int u = c * 8 + (nt >> 1) * 4 + (gid >> 1);
            int row = gate * 512 + u;
            float v0, v1;
            if (kt < 32) {
                int k = kt * 16 + (e & 1) * 8 + tig * 2;
                v0 = Wih1[row * HH + k]; v1 = Wih1[row * HH + k + 1];
            } else {
                int k = (kt - 32) * 16 + (e & 1) * 8 + tig * 2;
                v0 = Whh1[row * HH + k]; v1 = Whh1[row * HH + k + 1];
            }
            dst[idx] = f2h2(v0, v1);
        }
        // bias in acc-slot layout: [tl128][q4][e4]; gate=(q&1)*2+(e&1); u=c*8+(q>>1)*4+tig
        for (int idx = threadIdx.x; idx < 2048; idx += 256) {
            int e = idx & 3, q = (idx >> 2) & 3, tl = idx >> 4;
            int tig = tl & 3;
            int u = c * 8 + (q >> 1) * 4 + tig;
            int gate = (q & 1) * 2 + (e & 1);
            int row = gate * 512 + u;
            g_b2p[c * 2048 + idx] = bih1[row] + bhh1[row];
        }
    }
}

// acc-init for layer1 (fp16 output, up to 8 timesteps per block, bounds-guarded: TT % 8 != 0)
__global__ void xg0_kernel(const float* __restrict__ x, const float* __restrict__ Wih0,
                           const float* __restrict__ bih0, const float* __restrict__ bhh0) {
    __shared__ float ws[32][40];
    __shared__ float gsm[64][33];
    __shared__ float bsm[32];
    int c = blockIdx.x & 63, t0 = (blockIdx.x >> 6) * 8;
    int tid = threadIdx.x;
    for (int i = tid; i < 32 * FF; i += 256) {
        int rl = i / FF, f = i - rl * FF;
        int row = (rl >> 3) * 512 + c * 8 + (rl & 7);
        ws[rl][f] = Wih0[row * FF + f];
    }
    if (tid < 32) {
        int rl = tid;
        int row = (rl >> 3) * 512 + c * 8 + (rl & 7);
        bsm[rl] = bih0[row] + bhh0[row];
    }
    __syncthreads();
    int b = tid & 63, rq = tid >> 6;           // phase A roles
    int hq = tid >> 7, tl = tid & 127;         // phase B roles
    int mtb = tl >> 5, laneB = tl & 31;
    int gidB = laneB >> 2, tigB = laneB & 3;
    for (int tt = 0; tt < 8; tt++) {
        int t = t0 + tt;
        if (t >= TT) break;                    // uniform across block (t independent of tid)
        {   // phase A: outer product (x in regs, ws broadcast)
            float xr[36];
            const float4* xp = (const float4*)(x + ((size_t)b * TT + t) * FF);
#pragma unroll
            for (int f4 = 0; f4 < 9; f4++) {
                float4 v = __ldg(xp + f4);
                xr[f4 * 4] = v.x; xr[f4 * 4 + 1] = v.y;
                xr[f4 * 4 + 2] = v.z; xr[f4 * 4 + 3] = v.w;
            }
#pragma unroll
            for (int jr = 0; jr < 8; jr++) {
                int rl = rq * 8 + jr;
                const float4* wp = (const float4*)(&ws[rl][0]);
                float a = 0.f;
#pragma unroll
                for (int f4 = 0; f4 < 9; f4++) {
                    float4 w = wp[f4];
                    a = fmaf(xr[f4 * 4], w.x, a);
                    a = fmaf(xr[f4 * 4 + 1], w.y, a);
                    a = fmaf(xr[f4 * 4 + 2], w.z, a);
                    a = fmaf(xr[f4 * 4 + 3], w.w, a);
                }
                gsm[b][rl] = a;
            }
        }
        __syncthreads();
        {   // phase B: acc-slot packing, fp16 (one uint4 per thread)
            float v[8];
#pragma unroll
            for (int qq = 0; qq < 2; qq++) {
                int q = hq * 2 + qq;
                int uloc = (q >> 1) * 4 + tigB;
#pragma unroll
                for (int e = 0; e < 4; e++) {
                    int gate = (q & 1) * 2 + (e & 1);
                    int bb = mtb * 16 + gidB + 8 * (e >> 1);
                    v[qq * 4 + e] = bsm[gate * 8 + uloc] + gsm[bb][gate * 8 + uloc];
                }
            }
            uint4 o;
            o.x = f2h2(v[0], v[1]); o.y = f2h2(v[2], v[3]);
            o.z = f2h2(v[4], v[5]); o.w = f2h2(v[6], v[7]);
            *(uint4*)(g_xg0ph + (size_t)t * 65536 + c * 1024 + tl * 8 + hq * 4) = o;
        }
        __syncthreads();
    }
}

// ---------------- persistent 2-layer LSTM ----------------
// smem: Bs uint4[4096] (64KB weights) + EX float4[512] (8KB handoff)
#define SMEM_BYTES 73728

__global__ void __launch_bounds__(NT, 1) lstm_kernel() {
    extern __shared__ uint4 smemu[];
    uint4* Bs = smemu;
    float4* EX = (float4*)(smemu + 4096);

    const int cta = blockIdx.x;
    const int layer = cta >> 6;
    const int c = cta & 63;
    const int tid = threadIdx.x;
    const int ks = tid >> 7;               // k-split group; also owns uu = ks in the tail
    const int tl = tid & 127;
    const int mt = (tid >> 5) & 3;
    const int lane = tid & 31;
    const int gid = lane >> 2, tig = lane & 3;

    {   // weights -> smem
        const uint4* wsrc = (const uint4*)(layer ? (g_wf2 + c * 16384) : (g_wf1 + c * 8192));
        int tot = layer ? 4096 : 2048;
        for (int i = tid; i < tot; i += NT) Bs[i] = wsrc[i];
    }
    float bias16[16];
    if (layer && ks == 0) {
        const float4* bp = (const float4*)(g_b2p + c * 2048 + tl * 16);
#pragma unroll
        for (int q = 0; q < 4; q++) {
            float4 v = bp[q];
            bias16[q * 4] = v.x; bias16[q * 4 + 1] = v.y;
            bias16[q * 4 + 2] = v.z; bias16[q * 4 + 3] = v.w;
        }
    }
    float cst[2] = {0.f, 0.f};             // cell state for my uu=ks half (2 batches)
    __syncthreads();

    const int ktS = c >> 1;
    const int sbase = ((ktS * 4 + mt) * 32 + gid * 4 + (tig >> 1)) * 4 + 2 * (c & 1);
    const int hpar = tig & 1;
    const int myGrp = c >> 4;
    const int qa = ks * 2, qb = qa + 1;    // owned quads
    const int pa = (ks ^ 1) * 2, pb = pa + 1;

    for (int t = 0; t < TT; t++) {
        float acc[4][4];
        uint4 xa, xb;
        if (!layer) {
            if (ks == 0) {   // prefetch fp16 acc-init; applied AFTER the gemm (latency hidden)
                const uint4* xp = (const uint4*)(g_xg0ph + (size_t)t * 65536 + c * 1024 + tl * 8);
                xa = __ldcg(xp); xb = __ldcg(xp + 1);
            }
#pragma unroll
            for (int i = 0; i < 16; i++) acc[i >> 2][i & 3] = 0.f;
            const uint4* Ap = (const uint4*)(g_h1s + ((t - 1) & 3) * 16384) + ks * 2048 + mt * 32 + lane;
#pragma unroll
            for (int ch = 0; ch < 2; ch++) {
                waitflag(&g_f1[t].g[ks * 2 + ch], 128);
                gemm8(acc, Ap + ch * 1024, Bs + ks * 1024 + ch * 512 + lane);
            }
            if (ks == 0) {   // fold in xg (fp16 -> fp32)
                const __half2* hx = (const __half2*)&xa;
                const __half2* hy = (const __half2*)&xb;
#pragma unroll
                for (int k = 0; k < 4; k++) {
                    float2 p = __half22float2(hx[k]);
                    acc[k >> 1][(k & 1) * 2] += p.x;
                    acc[k >> 1][(k & 1) * 2 + 1] += p.y;
                }
#pragma unroll
                for (int k = 0; k < 4; k++) {
                    float2 p = __half22float2(hy[k]);
                    acc[2 + (k >> 1)][(k & 1) * 2] += p.x;
                    acc[2 + (k >> 1)][(k & 1) * 2 + 1] += p.y;
                }
            }
            if (t >= 4) waitflag4(&g_f2[t - 3], 128);   // ring guard, off the front
        } else {
            if (ks == 0) {
#pragma unroll
                for (int i = 0; i < 16; i++) acc[i >> 2][i & 3] = bias16[i];
            } else {
#pragma unroll
                for (int i = 0; i < 16; i++) acc[i >> 2][i & 3] = 0.f;
            }
            const uint4* Ap1 = (const uint4*)(g_h1s + (t & 3) * 16384) + ks * 2048 + mt * 32 + lane;
#pragma unroll
            for (int ch = 0; ch < 2; ch++) {
                waitflag(&g_f1[t + 1].g[ks * 2 + ch], 128);
                gemm8(acc, Ap1 + ch * 1024, Bs + ks * 1024 + ch * 512 + lane);
            }
            const uint4* Ap2 = (const uint4*)(g_h2s + ((t - 1) & 1) * 16384) + ks * 2048 + mt * 32 + lane;
#pragma unroll
            for (int ch = 0; ch < 2; ch++) {
                waitflag(&g_f2[t].g[ks * 2 + ch], 128);
                gemm8(acc, Ap2 + ch * 1024, Bs + 2048 + ks * 1024 + ch * 512 + lane);
            }
        }
        // symmetric handoff: ship the uu-half I don't own, keep mine
        EX[(ks ^ 1) * 256 + tl * 2]     = make_float4(acc[pa][0], acc[pa][1], acc[pa][2], acc[pa][3]);
        EX[(ks ^ 1) * 256 + tl * 2 + 1] = make_float4(acc[pb][0], acc[pb][1], acc[pb][2], acc[pb][3]);
        __syncthreads();
        {
            float4 fa = EX[ks * 256 + tl * 2];
            float4 fb = EX[ks * 256 + tl * 2 + 1];
            acc[qa][0] += fa.x; acc[qa][1] += fa.y; acc[qa][2] += fa.z; acc[qa][3] += fa.w;
            acc[qb][0] += fb.x; acc[qb][1] += fb.y; acc[qb][2] += fb.z; acc[qb][3] += fb.w;
            uint32_t* slab = layer ? (g_h2s + (t & 1) * 16384) : (g_h1s + (t & 3) * 16384);
            uint16_t* hp = (uint16_t*)slab;
#pragma unroll
            for (int bb = 0; bb < 2; bb++) {
                float iv = sigm(acc[qa][bb * 2]);
                float fv = sigm(acc[qa][bb * 2 + 1]);
                float gv = tanha(acc[qb][bb * 2]);
                float ov = sigm(acc[qb][bb * 2 + 1]);
                float cv = fmaf(fv, cst[bb], iv * gv);
                cst[bb] = cv;
                float hv = ov * tanha(cv);
                __half hh = __float2half_rn(hv);
                hp[(sbase + ks * 8 + bb) * 2 + hpar] = __half_as_ushort(hh);
            }
        }
        // per-warp early release (target 128 = 16 CTAs x 8 warps)
        __syncwarp();
        if (lane == 0) {
            unsigned* fp = layer ? &g_f2[t + 1].g[myGrp] : &g_f1[t + 1].g[myGrp];
            asm volatile("red.release.gpu.global.add.u32 [%0], 1;" ::"l"(fp) : "memory");
        }
        __syncthreads();   // EX reuse guard (off the release path)
    }
}

// ---------------- final projection ----------------
__global__ void out_kernel(const float* __restrict__ Wout, const float* __restrict__ bout,
                           float* __restrict__ out) {
    __shared__ float hs[512];
    int b = blockIdx.x;
    const uint32_t* slab = g_h2s + ((TT - 1) & 1) * 16384;
    for (int k = threadIdx.x; k < 512; k += 64) {
        int kt = k >> 4, ku = k & 15, mtb = b >> 4, r = b & 15;
        int laneS = (r & 7) * 4 + ((ku & 7) >> 1);
        int reg = (r >> 3) + 2 * (ku >> 3);
        uint32_t v = slab[((kt * 4 + mtb) * 32 + laneS) * 4 + reg];
        __half2 h2v = *reinterpret_cast<__half2*>(&v);
        hs[k] = (ku & 1) ? __high2float(h2v) : __low2float(h2v);
    }
    __syncthreads();
    int o = threadIdx.x;
    float acc = bout[o];
    const float* wr = Wout + o * HH;
#pragma unroll 8
    for (int k = 0; k < HH; k++) acc = fmaf(hs[k], wr[k], acc);
    out[b * 64 + o] = acc;
}

// ---------------- launch ----------------
extern "C" void kernel_launch(void* const* d_in, const int* in_sizes, int n_in,
                              void* d_out, int out_size) {
    const float* x    = (const float*)d_in[0];
    const float* Wih0 = (const float*)d_in[1];
    const float* Whh0 = (const float*)d_in[2];
    const float* bih0 = (const float*)d_in[3];
    const float* bhh0 = (const float*)d_in[4];
    const float* Wih1 = (const float*)d_in[5];
    const float* Whh1 = (const float*)d_in[6];
    const float* bih1 = (const float*)d_in[7];
    const float* bhh1 = (const float*)d_in[8];
    const float* Wout = (const float*)d_in[9];
    const float* bout = (const float*)d_in[10];
    float* out = (float*)d_out;

    cudaFuncSetAttribute(lstm_kernel, cudaFuncAttributeMaxDynamicSharedMemorySize, SMEM_BYTES);

    reset_kernel<<<64, 256>>>();
    pack_kernel<<<128, 256>>>(Whh0, Wih1, Whh1, bih1, bhh1);
    xg0_kernel<<<((TT + 7) / 8) * 64, 256>>>(x, Wih0, bih0, bhh0);   // ceil: TT % 8 != 0
    lstm_kernel<<<GRID, NT, SMEM_BYTES>>>();
    out_kernel<<<64, 64>>>(Wout, bout, out);
}

// round 13
// speedup vs baseline: 1.1017x; 1.1017x over previous
#include <cuda_runtime.h>
#include <cuda_fp16.h>
#include <cstdint>

#define BB 64
#define TT 1500
#define FF 36
#define HH 512
#define NT 256          // 8 warps: ks2 x mt4
#define GRID 128        // 64 CTAs per layer, 8 units per CTA

// ---------------- device globals ----------------
__device__ uint32_t g_xg0ph[(size_t)TT * 65536];  // 393MB fp16 acc-init [t][c64][tl128][16h]
__device__ float g_b2p[64 * 2048];                // layer2 bias  [c][tl128][q4][e4]
__device__ uint32_t g_wf1[64 * 8192];             // layer1 B-frags [c][kt32][p2][lane32][e4]
__device__ uint32_t g_wf2[64 * 16384];            // layer2 B-frags [c][kt64][p2][lane32][e4]
__device__ uint32_t g_h1s[4 * 16384];             // h1 ring, fp16 A-frag layout
__device__ uint32_t g_h2s[2 * 16384];             // h2 ring
// 4 group counters per (layer, step): group g = producer CTAs [16g,16g+16); target 16 (one red per CTA)
struct alignas(128) FlagG { unsigned g[4]; unsigned pad[28]; };
__device__ FlagG g_f1[TT + 2];
__device__ FlagG g_f2[TT + 2];

// ---------------- helpers ----------------
__device__ __forceinline__ float tanha(float x) {
    float y;
    asm("tanh.approx.f32 %0, %1;" : "=f"(y) : "f"(x));
    return y;
}
__device__ __forceinline__ float sigm(float x) { return fmaf(tanha(0.5f * x), 0.5f, 0.5f); }

__device__ __forceinline__ uint32_t f2h2(float lo, float hi) {
    __half2 h = __floats2half2_rn(lo, hi);
    return *reinterpret_cast<uint32_t*>(&h);
}

__device__ __forceinline__ void mma16(float* d, uint4 a, uint32_t b0, uint32_t b1) {
    asm volatile(
        "mma.sync.aligned.m16n8k16.row.col.f32.f16.f16.f32 "
        "{%0,%1,%2,%3},{%4,%5,%6,%7},{%8,%9},{%0,%1,%2,%3};\n"
        : "+f"(d[0]), "+f"(d[1]), "+f"(d[2]), "+f"(d[3])
        : "r"(a.x), "r"(a.y), "r"(a.z), "r"(a.w), "r"(b0), "r"(b1));
}

__device__ __forceinline__ void waitflag(const unsigned* p, unsigned tgt) {
    unsigned v;
    do {
        asm volatile("ld.acquire.gpu.global.u32 %0, [%1];" : "=r"(v) : "l"(p) : "memory");
    } while (v < tgt);
}
__device__ __forceinline__ void waitflag4(const FlagG* f, unsigned tgt) {
    unsigned a, b, c, d;
    do {
        asm volatile("ld.acquire.gpu.global.u32 %0, [%1];" : "=r"(a) : "l"(&f->g[0]) : "memory");
        asm volatile("ld.acquire.gpu.global.u32 %0, [%1];" : "=r"(b) : "l"(&f->g[1]) : "memory");
        asm volatile("ld.acquire.gpu.global.u32 %0, [%1];" : "=r"(c) : "l"(&f->g[2]) : "memory");
        asm volatile("ld.acquire.gpu.global.u32 %0, [%1];" : "=r"(d) : "l"(&f->g[3]) : "memory");
    } while (a < tgt || b < tgt || c < tgt || d < tgt);
}

// 8 k16-tiles: per kt: 1 LDG.128 (A) + 2 LDS.128 (B) + 4 MMA.
__device__ __forceinline__ void gemm8(float acc[4][4], const uint4* __restrict__ Ap,
                                      const uint4* __restrict__ Bp) {
    uint4 aq[8];
#pragma unroll
    for (int i = 0; i < 8; i++) aq[i] = __ldcg(Ap + i * 128);
#pragma unroll
    for (int i = 0; i < 8; i++) {
        uint4 av = aq[i];
        uint4 q1 = Bp[i * 64];
        uint4 q2 = Bp[i * 64 + 32];
        mma16(acc[0], av, q1.x, q1.y);
        mma16(acc[1], av, q1.z, q1.w);
        mma16(acc[2], av, q2.x, q2.y);
        mma16(acc[3], av, q2.z, q2.w);
    }
}

// ---------------- setup kernels ----------------
__global__ void reset_kernel() {
    int idx = blockIdx.x * 256 + threadIdx.x;
    if (idx < TT + 2) {
#pragma unroll
        for (int j = 0; j < 4; j++) {
            g_f1[idx].g[j] = (idx == 0) ? 16u : 0u;
            g_f2[idx].g[j] = (idx == 0) ? 16u : 0u;
        }
    }
    if (idx < 16384) {
        g_h1s[3 * 16384 + idx] = 0u;   // h1[-1] slab ((-1)&3 = 3)
        g_h2s[16384 + idx] = 0u;       // h2[-1] slab ((-1)&1 = 1)
    }
}

__global__ void pack_kernel(const float* __restrict__ Whh0, const float* __restrict__ Wih1,
                            const float* __restrict__ Whh1, const float* __restrict__ bih1,
                            const float* __restrict__ bhh1) {
    int cb = blockIdx.x;
    if (cb < 64) {
        int c = cb;
        uint32_t* dst = g_wf1 + c * 8192;
        for (int idx = threadIdx.x; idx < 8192; idx += 256) {
            int e = idx & 3, lane = (idx >> 2) & 31, p = (idx >> 7) & 1, kt = idx >> 8;
            int gid = lane >> 2, tig = lane & 3;
            int nt = 2 * p + (e >> 1);
            int gate = (nt & 1) * 2 + (gid & 1);
            int u = c * 8 + (nt >> 1) * 4 + (gid >> 1);
            int row = gate * 512 + u;
            int k = kt * 16 + (e & 1) * 8 + tig * 2;
            dst[idx] = f2h2(Whh0[row * HH + k], Whh0[row * HH + k + 1]);
        }
    } else {
        int c = cb - 64;
        uint32_t* dst = g_wf2 + c * 16384;
        for (int idx = threadIdx.x; idx < 16384; idx += 256) {
            int e = idx & 3, lane = (idx >> 2) & 31, p = (idx >> 7) & 1, kt = idx >> 8;
            int gid = lane >> 2, tig = lane & 3;
            int nt = 2 * p + (e >> 1);
            int gate = (nt & 1) * 2 + (gid & 1);
            int u = c * 8 + (nt >> 1) * 4 + (gid >> 1);
            int row = gate * 512 + u;
            float v0, v1;
            if (kt < 32) {
                int k = kt * 16 + (e & 1) * 8 + tig * 2;
                v0 = Wih1[row * HH + k]; v1 = Wih1[row * HH + k + 1];
            } else {
                int k = (kt - 32) * 16 + (e & 1) * 8 + tig * 2;
                v0 = Whh1[row * HH + k]; v1 = Whh1[row * HH + k + 1];
            }
            dst[idx] = f2h2(v0, v1);
        }
        // bias in acc-slot layout: [tl128][q4][e4]; gate=(q&1)*2+(e&1); u=c*8+(q>>1)*4+tig
        for (int idx = threadIdx.x; idx < 2048; idx += 256) {
            int e = idx & 3, q = (idx >> 2) & 3, tl = idx >> 4;
            int tig = tl & 3;
            int u = c * 8 + (q >> 1) * 4 + tig;
            int gate = (q & 1) * 2 + (e & 1);
            int row = gate * 512 + u;
            g_b2p[c * 2048 + idx] = bih1[row] + bhh1[row];
        }
    }
}

// acc-init for layer1 (fp16 output, up to 8 timesteps per block, bounds-guarded: TT % 8 != 0)
__global__ void xg0_kernel(const float* __restrict__ x, const float* __restrict__ Wih0,
                           const float* __restrict__ bih0, const float* __restrict__ bhh0) {
    __shared__ float ws[32][40];
    __shared__ float gsm[64][33];
    __shared__ float bsm[32];
    int c = blockIdx.x & 63, t0 = (blockIdx.x >> 6) * 8;
    int tid = threadIdx.x;
    for (int i = tid; i < 32 * FF; i += 256) {
        int rl = i / FF, f = i - rl * FF;
        int row = (rl >> 3) * 512 + c * 8 + (rl & 7);
        ws[rl][f] = Wih0[row * FF + f];
    }
    if (tid < 32) {
        int rl = tid;
        int row = (rl >> 3) * 512 + c * 8 + (rl & 7);
        bsm[rl] = bih0[row] + bhh0[row];
    }
    __syncthreads();
    int b = tid & 63, rq = tid >> 6;           // phase A roles
    int hq = tid >> 7, tl = tid & 127;         // phase B roles
    int mtb = tl >> 5, laneB = tl & 31;
    int gidB = laneB >> 2, tigB = laneB & 3;
    for (int tt = 0; tt < 8; tt++) {
        int t = t0 + tt;
        if (t >= TT) break;                    // uniform across block
        {   // phase A: outer product (x in regs, ws broadcast)
            float xr[36];
            const float4* xp = (const float4*)(x + ((size_t)b * TT + t) * FF);
#pragma unroll
            for (int f4 = 0; f4 < 9; f4++) {
                float4 v = __ldg(xp + f4);
                xr[f4 * 4] = v.x; xr[f4 * 4 + 1] = v.y;
                xr[f4 * 4 + 2] = v.z; xr[f4 * 4 + 3] = v.w;
            }
#pragma unroll
            for (int jr = 0; jr < 8; jr++) {
                int rl = rq * 8 + jr;
                const float4* wp = (const float4*)(&ws[rl][0]);
                float a = 0.f;
#pragma unroll
                for (int f4 = 0; f4 < 9; f4++) {
                    float4 w = wp[f4];
                    a = fmaf(xr[f4 * 4], w.x, a);
                    a = fmaf(xr[f4 * 4 + 1], w.y, a);
                    a = fmaf(xr[f4 * 4 + 2], w.z, a);
                    a = fmaf(xr[f4 * 4 + 3], w.w, a);
                }
                gsm[b][rl] = a;
            }
        }
        __syncthreads();
        {   // phase B: acc-slot packing, fp16 (one uint4 per thread)
            float v[8];
#pragma unroll
            for (int qq = 0; qq < 2; qq++) {
                int q = hq * 2 + qq;
                int uloc = (q >> 1) * 4 + tigB;
#pragma unroll
                for (int e = 0; e < 4; e++) {
                    int gate = (q & 1) * 2 + (e & 1);
                    int bb = mtb * 16 + gidB + 8 * (e >> 1);
                    v[qq * 4 + e] = bsm[gate * 8 + uloc] + gsm[bb][gate * 8 + uloc];
                }
            }
            uint4 o;
            o.x = f2h2(v[0], v[1]); o.y = f2h2(v[2], v[3]);
            o.z = f2h2(v[4], v[5]); o.w = f2h2(v[6], v[7]);
            *(uint4*)(g_xg0ph + (size_t)t * 65536 + c * 1024 + tl * 8 + hq * 4) = o;
        }
        __syncthreads();
    }
}

// ---------------- persistent 2-layer LSTM ----------------
// smem: Bs uint4[4096] (64KB weights) + EX float4[512] (8KB handoff)
#define SMEM_BYTES 73728

__global__ void __launch_bounds__(NT, 1) lstm_kernel() {
    extern __shared__ uint4 smemu[];
    uint4* Bs = smemu;
    float4* EX = (float4*)(smemu + 4096);

    const int cta = blockIdx.x;
    const int layer = cta >> 6;
    const int c = cta & 63;
    const int tid = threadIdx.x;
    const int ks = tid >> 7;               // k-split group; also owns uu = ks in the tail
    const int tl = tid & 127;
    const int mt = (tid >> 5) & 3;
    const int lane = tid & 31;
    const int gid = lane >> 2, tig = lane & 3;

    {   // weights -> smem
        const uint4* wsrc = (const uint4*)(layer ? (g_wf2 + c * 16384) : (g_wf1 + c * 8192));
        int tot = layer ? 4096 : 2048;
        for (int i = tid; i < tot; i += NT) Bs[i] = wsrc[i];
    }
    float bias16[16];
    if (layer && ks == 0) {
        const float4* bp = (const float4*)(g_b2p + c * 2048 + tl * 16);
#pragma unroll
        for (int q = 0; q < 4; q++) {
            float4 v = bp[q];
            bias16[q * 4] = v.x; bias16[q * 4 + 1] = v.y;
            bias16[q * 4 + 2] = v.z; bias16[q * 4 + 3] = v.w;
        }
    }
    float cst[2] = {0.f, 0.f};             // cell state for my uu=ks half (2 batches)
    __syncthreads();

    const int ktS = c >> 1;
    const int sbase = ((ktS * 4 + mt) * 32 + gid * 4 + (tig >> 1)) * 4 + 2 * (c & 1);
    const int hpar = tig & 1;
    const int myGrp = c >> 4;
    const int qa = ks * 2, qb = qa + 1;    // owned quads
    const int pa = (ks ^ 1) * 2, pb = pa + 1;

    for (int t = 0; t < TT; t++) {
        float acc[4][4];
        uint4 xa, xb;
        if (!layer) {
            if (ks == 0) {   // prefetch fp16 acc-init; applied AFTER the gemm (latency hidden)
                const uint4* xp = (const uint4*)(g_xg0ph + (size_t)t * 65536 + c * 1024 + tl * 8);
                xa = __ldcg(xp); xb = __ldcg(xp + 1);
            }
#pragma unroll
            for (int i = 0; i < 16; i++) acc[i >> 2][i & 3] = 0.f;
            const uint4* Ap = (const uint4*)(g_h1s + ((t - 1) & 3) * 16384) + ks * 2048 + mt * 32 + lane;
#pragma unroll
            for (int ch = 0; ch < 2; ch++) {
                waitflag(&g_f1[t].g[ks * 2 + ch], 16);
                gemm8(acc, Ap + ch * 1024, Bs + ks * 1024 + ch * 512 + lane);
            }
            if (ks == 0) {   // fold in xg (fp16 -> fp32)
                const __half2* hx = (const __half2*)&xa;
                const __half2* hy = (const __half2*)&xb;
#pragma unroll
                for (int k = 0; k < 4; k++) {
                    float2 p = __half22float2(hx[k]);
                    acc[k >> 1][(k & 1) * 2] += p.x;
                    acc[k >> 1][(k & 1) * 2 + 1] += p.y;
                }
#pragma unroll
                for (int k = 0; k < 4; k++) {
                    float2 p = __half22float2(hy[k]);
                    acc[2 + (k >> 1)][(k & 1) * 2] += p.x;
                    acc[2 + (k >> 1)][(k & 1) * 2 + 1] += p.y;
                }
            }
            if (t >= 4) waitflag4(&g_f2[t - 3], 16);   // ring guard, off the front
        } else {
            if (ks == 0) {
#pragma unroll
                for (int i = 0; i < 16; i++) acc[i >> 2][i & 3] = bias16[i];
            } else {
#pragma unroll
                for (int i = 0; i < 16; i++) acc[i >> 2][i & 3] = 0.f;
            }
            const uint4* Ap1 = (const uint4*)(g_h1s + (t & 3) * 16384) + ks * 2048 + mt * 32 + lane;
#pragma unroll
            for (int ch = 0; ch < 2; ch++) {
                waitflag(&g_f1[t + 1].g[ks * 2 + ch], 16);
                gemm8(acc, Ap1 + ch * 1024, Bs + ks * 1024 + ch * 512 + lane);
            }
            const uint4* Ap2 = (const uint4*)(g_h2s + ((t - 1) & 1) * 16384) + ks * 2048 + mt * 32 + lane;
#pragma unroll
            for (int ch = 0; ch < 2; ch++) {
                waitflag(&g_f2[t].g[ks * 2 + ch], 16);
                gemm8(acc, Ap2 + ch * 1024, Bs + 2048 + ks * 1024 + ch * 512 + lane);
            }
        }
        // symmetric handoff: ship the uu-half I don't own, keep mine
        EX[(ks ^ 1) * 256 + tl * 2]     = make_float4(acc[pa][0], acc[pa][1], acc[pa][2], acc[pa][3]);
        EX[(ks ^ 1) * 256 + tl * 2 + 1] = make_float4(acc[pb][0], acc[pb][1], acc[pb][2], acc[pb][3]);
        __syncthreads();
        {
            float4 fa = EX[ks * 256 + tl * 2];
            float4 fb = EX[ks * 256 + tl * 2 + 1];
            acc[qa][0] += fa.x; acc[qa][1] += fa.y; acc[qa][2] += fa.z; acc[qa][3] += fa.w;
            acc[qb][0] += fb.x; acc[qb][1] += fb.y; acc[qb][2] += fb.z; acc[qb][3] += fb.w;
            uint32_t* slab = layer ? (g_h2s + (t & 1) * 16384) : (g_h1s + (t & 3) * 16384);
            uint16_t* hp = (uint16_t*)slab;
#pragma unroll
            for (int bb = 0; bb < 2; bb++) {
                float iv = sigm(acc[qa][bb * 2]);
                float fv = sigm(acc[qa][bb * 2 + 1]);
                float gv = tanha(acc[qb][bb * 2]);
                float ov = sigm(acc[qb][bb * 2 + 1]);
                float cv = fmaf(fv, cst[bb], iv * gv);
                cst[bb] = cv;
                float hv = ov * tanha(cv);
                __half hh = __float2half_rn(hv);
                hp[(sbase + ks * 8 + bb) * 2 + hpar] = __half_as_ushort(hh);
            }
        }
        // single release per CTA (reverted: 16 atomics per flag word, not 128)
        __syncthreads();   // h-stores + EX reuse guard
        if (tid == 0) {
            unsigned* fp = layer ? &g_f2[t + 1].g[myGrp] : &g_f1[t + 1].g[myGrp];
            asm volatile("red.release.gpu.global.add.u32 [%0], 1;" ::"l"(fp) : "memory");
        }
    }
}

// ---------------- final projection ----------------
__global__ void out_kernel(const float* __restrict__ Wout, const float* __restrict__ bout,
                           float* __restrict__ out) {
    __shared__ float hs[512];
    int b = blockIdx.x;
    const uint32_t* slab = g_h2s + ((TT - 1) & 1) * 16384;
    for (int k = threadIdx.x; k < 512; k += 64) {
        int kt = k >> 4, ku = k & 15, mtb = b >> 4, r = b & 15;
        int laneS = (r & 7) * 4 + ((ku & 7) >> 1);
        int reg = (r >> 3) + 2 * (ku >> 3);
        uint32_t v = slab[((kt * 4 + mtb) * 32 + laneS) * 4 + reg];
        __half2 h2v = *reinterpret_cast<__half2*>(&v);
        hs[k] = (ku & 1) ? __high2float(h2v) : __low2float(h2v);
    }
    __syncthreads();
    int o = threadIdx.x;
    float acc = bout[o];
    const float* wr = Wout + o * HH;
#pragma unroll 8
    for (int k = 0; k < HH; k++) acc = fmaf(hs[k], wr[k], acc);
    out[b * 64 + o] = acc;
}

// ---------------- launch ----------------
extern "C" void kernel_launch(void* const* d_in, const int* in_sizes, int n_in,
                              void* d_out, int out_size) {
    const float* x    = (const float*)d_in[0];
    const float* Wih0 = (const float*)d_in[1];
    const float* Whh0 = (const float*)d_in[2];
    const float* bih0 = (const float*)d_in[3];
    const float* bhh0 = (const float*)d_in[4];
    const float* Wih1 = (const float*)d_in[5];
    const float* Whh1 = (const float*)d_in[6];
    const float* bih1 = (const float*)d_in[7];
    const float* bhh1 = (const float*)d_in[8];
    const float* Wout = (const float*)d_in[9];
    const float* bout = (const float*)d_in[10];
    float* out = (float*)d_out;

    cudaFuncSetAttribute(lstm_kernel, cudaFuncAttributeMaxDynamicSharedMemorySize, SMEM_BYTES);

    reset_kernel<<<64, 256>>>();
    pack_kernel<<<128, 256>>>(Whh0, Wih1, Whh1, bih1, bhh1);
    xg0_kernel<<<((TT + 7) / 8) * 64, 256>>>(x, Wih0, bih0, bhh0);   // ceil: TT % 8 != 0
    lstm_kernel<<<GRID, NT, SMEM_BYTES>>>();
    out_kernel<<<64, 64>>>(Wout, bout, out);
}

// round 14
// speedup vs baseline: 1.1357x; 1.0309x over previous
#include <cuda_runtime.h>
#include <cuda_fp16.h>
#include <cstdint>

#define BB 64
#define TT 1500
#define FF 36
#define HH 512
#define NT 256          // 8 warps: kq4 x mh2; each warp m32 x n32
#define GRID 128        // 64 CTAs per layer, 8 units per CTA

// ---------------- device globals ----------------
__device__ uint32_t g_xg0ph[(size_t)TT * 65536];  // 393MB fp16 acc-init [t][c64][tl128][16h]
__device__ float g_b2p[64 * 2048];                // layer2 bias  [c][tl128][q4][e4]
__device__ uint32_t g_wf1[64 * 8192];             // layer1 B-frags [c][kt32][p2][lane32][e4]
__device__ uint32_t g_wf2[64 * 16384];            // layer2 B-frags [c][kt64][p2][lane32][e4]
__device__ uint32_t g_h1s[4 * 16384];             // h1 ring, fp16 A-frag layout [kt][mt4][lane32][reg4]
__device__ uint32_t g_h2s[2 * 16384];             // h2 ring
// 4 group counters per (layer, step): group g = producer CTAs [16g,16g+16) = kt range [8g,8g+8); target 16
struct alignas(128) FlagG { unsigned g[4]; unsigned pad[28]; };
__device__ FlagG g_f1[TT + 2];
__device__ FlagG g_f2[TT + 2];

// ---------------- helpers ----------------
__device__ __forceinline__ float tanha(float x) {
    float y;
    asm("tanh.approx.f32 %0, %1;" : "=f"(y) : "f"(x));
    return y;
}
__device__ __forceinline__ float sigm(float x) { return fmaf(tanha(0.5f * x), 0.5f, 0.5f); }

__device__ __forceinline__ uint32_t f2h2(float lo, float hi) {
    __half2 h = __floats2half2_rn(lo, hi);
    return *reinterpret_cast<uint32_t*>(&h);
}

__device__ __forceinline__ void mma16(float* d, uint4 a, uint32_t b0, uint32_t b1) {
    asm volatile(
        "mma.sync.aligned.m16n8k16.row.col.f32.f16.f16.f32 "
        "{%0,%1,%2,%3},{%4,%5,%6,%7},{%8,%9},{%0,%1,%2,%3};\n"
        : "+f"(d[0]), "+f"(d[1]), "+f"(d[2]), "+f"(d[3])
        : "r"(a.x), "r"(a.y), "r"(a.z), "r"(a.w), "r"(b0), "r"(b1));
}

__device__ __forceinline__ void waitflag(const unsigned* p, unsigned tgt) {
    unsigned v;
    do {
        asm volatile("ld.acquire.gpu.global.u32 %0, [%1];" : "=r"(v) : "l"(p) : "memory");
    } while (v < tgt);
}
__device__ __forceinline__ void waitflag4(const FlagG* f, unsigned tgt) {
    unsigned a, b, c, d;
    do {
        asm volatile("ld.acquire.gpu.global.u32 %0, [%1];" : "=r"(a) : "l"(&f->g[0]) : "memory");
        asm volatile("ld.acquire.gpu.global.u32 %0, [%1];" : "=r"(b) : "l"(&f->g[1]) : "memory");
        asm volatile("ld.acquire.gpu.global.u32 %0, [%1];" : "=r"(c) : "l"(&f->g[2]) : "memory");
        asm volatile("ld.acquire.gpu.global.u32 %0, [%1];" : "=r"(d) : "l"(&f->g[3]) : "memory");
    } while (a < tgt || b < tgt || c < tgt || d < tgt);
}

// 8 k16-tiles, TWO m16 tiles per warp: per kt: 2 LDG.128 (A) + 2 LDS.128 (B) + 8 MMA.
__device__ __forceinline__ void gemm8x2(float acc[2][4][4], const uint4* __restrict__ Ap,
                                        const uint4* __restrict__ Bp) {
    uint4 a0[4], a1[4];
#pragma unroll
    for (int i = 0; i < 4; i++) {
        a0[i] = __ldcg(Ap + i * 128);
        a1[i] = __ldcg(Ap + i * 128 + 32);
    }
#pragma unroll
    for (int i = 0; i < 8; i++) {
        uint4 av0 = a0[i & 3], av1 = a1[i & 3];
        uint4 q1 = Bp[i * 64];
        uint4 q2 = Bp[i * 64 + 32];
        if (i < 4) {
            a0[i & 3] = __ldcg(Ap + (i + 4) * 128);
            a1[i & 3] = __ldcg(Ap + (i + 4) * 128 + 32);
        }
        mma16(acc[0][0], av0, q1.x, q1.y);
        mma16(acc[0][1], av0, q1.z, q1.w);
        mma16(acc[0][2], av0, q2.x, q2.y);
        mma16(acc[0][3], av0, q2.z, q2.w);
        mma16(acc[1][0], av1, q1.x, q1.y);
        mma16(acc[1][1], av1, q1.z, q1.w);
        mma16(acc[1][2], av1, q2.x, q2.y);
        mma16(acc[1][3], av1, q2.z, q2.w);
    }
}

// ---------------- setup kernels ----------------
__global__ void reset_kernel() {
    int idx = blockIdx.x * 256 + threadIdx.x;
    if (idx < TT + 2) {
#pragma unroll
        for (int j = 0; j < 4; j++) {
            g_f1[idx].g[j] = (idx == 0) ? 16u : 0u;
            g_f2[idx].g[j] = (idx == 0) ? 16u : 0u;
        }
    }
    if (idx < 16384) {
        g_h1s[3 * 16384 + idx] = 0u;   // h1[-1] slab ((-1)&3 = 3)
        g_h2s[16384 + idx] = 0u;       // h2[-1] slab ((-1)&1 = 1)
    }
}

__global__ void pack_kernel(const float* __restrict__ Whh0, const float* __restrict__ Wih1,
                            const float* __restrict__ Whh1, const float* __restrict__ bih1,
                            const float* __restrict__ bhh1) {
    int cb = blockIdx.x;
    if (cb < 64) {
        int c = cb;
        uint32_t* dst = g_wf1 + c * 8192;
        for (int idx = threadIdx.x; idx < 8192; idx += 256) {
            int e = idx & 3, lane = (idx >> 2) & 31, p = (idx >> 7) & 1, kt = idx >> 8;
            int gid = lane >> 2, tig = lane & 3;
            int nt = 2 * p + (e >> 1);
            int gate = (nt & 1) * 2 + (gid & 1);
            int u = c * 8 + (nt >> 1) * 4 + (gid >> 1);
            int row = gate * 512 + u;
            int k = kt * 16 + (e & 1) * 8 + tig * 2;
            dst[idx] = f2h2(Whh0[row * HH + k], Whh0[row * HH + k + 1]);
        }
    } else {
        int c = cb - 64;
        uint32_t* dst = g_wf2 + c * 16384;
        for (int idx = threadIdx.x; idx < 16384; idx += 256) {
            int e = idx & 3, lane = (idx >> 2) & 31, p = (idx >> 7) & 1, kt = idx >> 8;
            int gid = lane >> 2, tig = lane & 3;
            int nt = 2 * p + (e >> 1);
            int gate = (nt & 1) * 2 + (gid & 1);
            int u = c * 8 + (nt >> 1) * 4 + (gid >> 1);
            int row = gate * 512 + u;
            float v0, v1;
            if (kt < 32) {
                int k = kt * 16 + (e & 1) * 8 + tig * 2;
                v0 = Wih1[row * HH + k]; v1 = Wih1[row * HH + k + 1];
            } else {
                int k = (kt - 32) * 16 + (e & 1) * 8 + tig * 2;
                v0 = Whh1[row * HH + k]; v1 = Whh1[row * HH + k + 1];
            }
            dst[idx] = f2h2(v0, v1);
        }
        // bias in acc-slot layout: [tl128][q4][e4]; gate=(q&1)*2+(e&1); u=c*8+(q>>1)*4+tig
        for (int idx = threadIdx.x; idx < 2048; idx += 256) {
            int e = idx & 3, q = (idx >> 2) & 3, tl = idx >> 4;
            int tig = tl & 3;
            int u = c * 8 + (q >> 1) * 4 + tig;
            int gate = (q & 1) * 2 + (e & 1);
            int row = gate * 512 + u;
            g_b2p[c * 2048 + idx] = bih1[row] + bhh1[row];
        }
    }
}

// acc-init for layer1 (fp16 output, up to 8 timesteps per block, bounds-guarded)
__global__ void xg0_kernel(const float* __restrict__ x, const float* __restrict__ Wih0,
                           const float* __restrict__ bih0, const float* __restrict__ bhh0) {
    __shared__ float ws[32][40];
    __shared__ float gsm[64][33];
    __shared__ float bsm[32];
    int c = blockIdx.x & 63, t0 = (blockIdx.x >> 6) * 8;
    int tid = threadIdx.x;
    for (int i = tid; i < 32 * FF; i += 256) {
        int rl = i / FF, f = i - rl * FF;
        int row = (rl >> 3) * 512 + c * 8 + (rl & 7);
        ws[rl][f] = Wih0[row * FF + f];
    }
    if (tid < 32) {
        int rl = tid;
        int row = (rl >> 3) * 512 + c * 8 + (rl & 7);
        bsm[rl] = bih0[row] + bhh0[row];
    }
    __syncthreads();
    int b = tid & 63, rq = tid >> 6;           // phase A roles
    int hq = tid >> 7, tl = tid & 127;         // phase B roles
    int mtb = tl >> 5, laneB = tl & 31;
    int gidB = laneB >> 2, tigB = laneB & 3;
    for (int tt = 0; tt < 8; tt++) {
        int t = t0 + tt;
        if (t >= TT) break;                    // uniform across block
        {   // phase A: outer product (x in regs, ws broadcast)
            float xr[36];
            const float4* xp = (const float4*)(x + ((size_t)b * TT + t) * FF);
#pragma unroll
            for (int f4 = 0; f4 < 9; f4++) {
                float4 v = __ldg(xp + f4);
                xr[f4 * 4] = v.x; xr[f4 * 4 + 1] = v.y;
                xr[f4 * 4 + 2] = v.z; xr[f4 * 4 + 3] = v.w;
            }
#pragma unroll
            for (int jr = 0; jr < 8; jr++) {
                int rl = rq * 8 + jr;
                const float4* wp = (const float4*)(&ws[rl][0]);
                float a = 0.f;
#pragma unroll
                for (int f4 = 0; f4 < 9; f4++) {
                    float4 w = wp[f4];
                    a = fmaf(xr[f4 * 4], w.x, a);
                    a = fmaf(xr[f4 * 4 + 1], w.y, a);
                    a = fmaf(xr[f4 * 4 + 2], w.z, a);
                    a = fmaf(xr[f4 * 4 + 3], w.w, a);
                }
                gsm[b][rl] = a;
            }
        }
        __syncthreads();
        {   // phase B: acc-slot packing, fp16
            float v[8];
#pragma unroll
            for (int qq = 0; qq < 2; qq++) {
                int q = hq * 2 + qq;
                int uloc = (q >> 1) * 4 + tigB;
#pragma unroll
                for (int e = 0; e < 4; e++) {
                    int gate = (q & 1) * 2 + (e & 1);
                    int bb = mtb * 16 + gidB + 8 * (e >> 1);
                    v[qq * 4 + e] = bsm[gate * 8 + uloc] + gsm[bb][gate * 8 + uloc];
                }
            }
            uint4 o;
            o.x = f2h2(v[0], v[1]); o.y = f2h2(v[2], v[3]);
            o.z = f2h2(v[4], v[5]); o.w = f2h2(v[6], v[7]);
            *(uint4*)(g_xg0ph + (size_t)t * 65536 + c * 1024 + tl * 8 + hq * 4) = o;
        }
        __syncthreads();
    }
}

// ---------------- persistent 2-layer LSTM ----------------
// smem: Bs uint4[4096] (64KB weights) + EX float4[2048] (32KB 4-way reduction)
#define SMEM_BYTES 98304

__global__ void __launch_bounds__(NT, 1) lstm_kernel() {
    extern __shared__ uint4 smemu[];
    uint4* Bs = smemu;
    float4* EX = (float4*)(smemu + 4096);

    const int cta = blockIdx.x;
    const int layer = cta >> 6;
    const int c = cta & 63;
    const int tid = threadIdx.x;
    const int w = tid >> 5;
    const int kq = w & 3;                  // k-quarter (= producer flag group for A reads)
    const int mh = w >> 2;                 // m-half (m32)
    const int lane = tid & 31;
    const int gid = lane >> 2, tig = lane & 3;
    const int P = kq >> 1;                 // owned nt-pair (uu-half)
    const int mI = kq & 1;                 // owned m-tile within the warp's m32
    const int mtS = mh * 2 + mI;           // owned global m16 tile
    const int tlo = mtS * 32 + lane;       // owner slot in [tl128] layouts

    {   // weights -> smem
        const uint4* wsrc = (const uint4*)(layer ? (g_wf2 + c * 16384) : (g_wf1 + c * 8192));
        int tot = layer ? 4096 : 2048;
        for (int i = tid; i < tot; i += NT) Bs[i] = wsrc[i];
    }
    float bias8[8];
    if (layer) {
        const float4* bp = (const float4*)(g_b2p + c * 2048 + tlo * 16 + P * 8);
        float4 v0 = bp[0], v1 = bp[1];
        bias8[0] = v0.x; bias8[1] = v0.y; bias8[2] = v0.z; bias8[3] = v0.w;
        bias8[4] = v1.x; bias8[5] = v1.y; bias8[6] = v1.z; bias8[7] = v1.w;
    }
    float cst[2] = {0.f, 0.f};             // 2 owned cells (batches bb=0,1)
    __syncthreads();

    const int ktS = c >> 1;
    const int sbase = ((ktS * 4 + mtS) * 32 + gid * 4 + P * 2 + (tig >> 1)) * 4 + 2 * (c & 1);
    const int hpar = tig & 1;
    const int myGrp = c >> 4;

    for (int t = 0; t < TT; t++) {
        float acc[2][4][4];
#pragma unroll
        for (int i = 0; i < 32; i++) acc[i >> 4][(i >> 2) & 3][i & 3] = 0.f;
        uint4 xg;
        if (!layer) {
            // owner prefetch of fp16 acc-init (one uint4); folded after reduction
            xg = __ldcg((const uint4*)(g_xg0ph + (size_t)t * 65536 + c * 1024 + tlo * 8 + P * 4));
            const uint4* Ap = (const uint4*)(g_h1s + ((t - 1) & 3) * 16384) + kq * 1024 + mh * 64 + lane;
            waitflag(&g_f1[t].g[kq], 16);              // exactly this warp's kt range
            gemm8x2(acc, Ap, Bs + kq * 512 + lane);
            if (t >= 4) waitflag4(&g_f2[t - 3], 16);   // ring guard, off the front
        } else {
            const uint4* Ap1 = (const uint4*)(g_h1s + (t & 3) * 16384) + kq * 1024 + mh * 64 + lane;
            waitflag(&g_f1[t + 1].g[kq], 16);          // h1[t] (layer1 runs ahead)
            gemm8x2(acc, Ap1, Bs + kq * 512 + lane);   // W_ih1 quarter
            const uint4* Ap2 = (const uint4*)(g_h2s + ((t - 1) & 1) * 16384) + kq * 1024 + mh * 64 + lane;
            waitflag(&g_f2[t].g[kq], 16);              // h2[t-1] — serial dep
            gemm8x2(acc, Ap2, Bs + 2048 + kq * 512 + lane);  // W_hh1 quarter
        }
        // ship the 3 unowned (mi, nt-pair) chunks; EX idx = (((mtS'*2 + p)*4 + srcKq)*32 + lane)*2
#pragma unroll
        for (int mi = 0; mi < 2; mi++) {
#pragma unroll
            for (int p = 0; p < 2; p++) {
                if (mi == mI && p == P) continue;      // keep own chunk in regs
                int oidx = ((((mh * 2 + mi) * 2 + p) * 4 + kq) * 32 + lane) * 2;
                EX[oidx]     = make_float4(acc[mi][p * 2][0], acc[mi][p * 2][1],
                                           acc[mi][p * 2][2], acc[mi][p * 2][3]);
                EX[oidx + 1] = make_float4(acc[mi][p * 2 + 1][0], acc[mi][p * 2 + 1][1],
                                           acc[mi][p * 2 + 1][2], acc[mi][p * 2 + 1][3]);
            }
        }
        __syncthreads();
        {
            float v[8];
#pragma unroll
            for (int e = 0; e < 4; e++) { v[e] = acc[mI][P * 2][e]; v[4 + e] = acc[mI][P * 2 + 1][e]; }
#pragma unroll
            for (int src = 0; src < 4; src++) {
                if (src == kq) continue;
                int iidx = (((mtS * 2 + P) * 4 + src) * 32 + lane) * 2;
                float4 fa = EX[iidx], fb = EX[iidx + 1];
                v[0] += fa.x; v[1] += fa.y; v[2] += fa.z; v[3] += fa.w;
                v[4] += fb.x; v[5] += fb.y; v[6] += fb.z; v[7] += fb.w;
            }
            if (!layer) {
                const __half2* hx = (const __half2*)&xg;
#pragma unroll
                for (int k = 0; k < 4; k++) {
                    float2 p2 = __half22float2(hx[k]);
                    v[k * 2] += p2.x; v[k * 2 + 1] += p2.y;
                }
            } else {
#pragma unroll
                for (int k = 0; k < 8; k++) v[k] += bias8[k];
            }
            uint32_t* slab = layer ? (g_h2s + (t & 1) * 16384) : (g_h1s + (t & 3) * 16384);
            uint16_t* hp = (uint16_t*)slab;
#pragma unroll
            for (int bb = 0; bb < 2; bb++) {
                float iv = sigm(v[bb * 2]);
                float fv = sigm(v[bb * 2 + 1]);
                float gv = tanha(v[4 + bb * 2]);
                float ov = sigm(v[4 + bb * 2 + 1]);
                float cv = fmaf(fv, cst[bb], iv * gv);
                cst[bb] = cv;
                float hv = ov * tanha(cv);
                __half hh = __float2half_rn(hv);
                hp[(sbase + bb) * 2 + hpar] = __half_as_ushort(hh);
            }
        }
        __syncthreads();   // h-stores + EX reuse guard
        if (tid == 0) {
            unsigned* fp = layer ? &g_f2[t + 1].g[myGrp] : &g_f1[t + 1].g[myGrp];
            asm volatile("red.release.gpu.global.add.u32 [%0], 1;" ::"l"(fp) : "memory");
        }
    }
}

// ---------------- final projection ----------------
__global__ void out_kernel(const float* __restrict__ Wout, const float* __restrict__ bout,
                           float* __restrict__ out) {
    __shared__ float hs[512];
    int b = blockIdx.x;
    const uint32_t* slab = g_h2s + ((TT - 1) & 1) * 16384;
    for (int k = threadIdx.x; k < 512; k += 64) {
        int kt = k >> 4, ku = k & 15, mtb = b >> 4, r = b & 15;
        int laneS = (r & 7) * 4 + ((ku & 7) >> 1);
        int reg = (r >> 3) + 2 * (ku >> 3);
        uint32_t v = slab[((kt * 4 + mtb) * 32 + laneS) * 4 + reg];
        __half2 h2v = *reinterpret_cast<__half2*>(&v);
        hs[k] = (ku & 1) ? __high2float(h2v) : __low2float(h2v);
    }
    __syncthreads();
    int o = threadIdx.x;
    float acc = bout[o];
    const float* wr = Wout + o * HH;
#pragma unroll 8
    for (int k = 0; k < HH; k++) acc = fmaf(hs[k], wr[k], acc);
    out[b * 64 + o] = acc;
}

// ---------------- launch ----------------
extern "C" void kernel_launch(void* const* d_in, const int* in_sizes, int n_in,
                              void* d_out, int out_size) {
    const float* x    = (const float*)d_in[0];
    const float* Wih0 = (const float*)d_in[1];
    const float* Whh0 = (const float*)d_in[2];
    const float* bih0 = (const float*)d_in[3];
    const float* bhh0 = (const float*)d_in[4];
    const float* Wih1 = (const float*)d_in[5];
    const float* Whh1 = (const float*)d_in[6];
    const float* bih1 = (const float*)d_in[7];
    const float* bhh1 = (const float*)d_in[8];
    const float* Wout = (const float*)d_in[9];
    const float* bout = (const float*)d_in[10];
    float* out = (float*)d_out;

    cudaFuncSetAttribute(lstm_kernel, cudaFuncAttributeMaxDynamicSharedMemorySize, SMEM_BYTES);

    reset_kernel<<<64, 256>>>();
    pack_kernel<<<128, 256>>>(Whh0, Wih1, Whh1, bih1, bhh1);
    xg0_kernel<<<((TT + 7) / 8) * 64, 256>>>(x, Wih0, bih0, bhh0);
    lstm_kernel<<<GRID, NT, SMEM_BYTES>>>();
    out_kernel<<<64, 64>>>(Wout, bout, out);
}

// round 15
// speedup vs baseline: 1.3413x; 1.1811x over previous
#include <cuda_runtime.h>
#include <cuda_fp16.h>
#include <cstdint>

#define BB 64
#define TT 1500
#define FF 36
#define HH 512
#define NT 256          // 8 warps: kq4 x mh2; each warp m32 x n32
#define GRID 128        // 64 CTAs per layer, 8 units per CTA

// ---------------- device globals ----------------
__device__ uint32_t g_xg0ph[(size_t)TT * 65536];  // 393MB fp16 acc-init [t][c64][tl128][16h]
__device__ uint32_t g_xf[(size_t)TT * 1536];      // 9.2MB x fp16 A-frags [t][kt3][mt4][lane32][reg4]
__device__ float g_b2p[64 * 2048];                // layer2 bias  [c][tl128][q4][e4]
__device__ float g_b1p[64 * 32];                  // layer1 bias rows [c][rl32]
__device__ uint32_t g_wf1[64 * 8192];             // layer1 B-frags [c][kt32][p2][lane32][e4]
__device__ uint32_t g_wf2[64 * 16384];            // layer2 B-frags [c][kt64][p2][lane32][e4]
__device__ uint32_t g_wfx[64 * 768];              // W_ih0 B-frags [c][kt3][p2][lane32][e4] (K pad 48)
__device__ uint32_t g_h1s[4 * 16384];             // h1 ring, fp16 A-frag layout
__device__ uint32_t g_h2s[2 * 16384];             // h2 ring
struct alignas(128) FlagG { unsigned g[4]; unsigned pad[28]; };
__device__ FlagG g_f1[TT + 2];
__device__ FlagG g_f2[TT + 2];

// ---------------- helpers ----------------
__device__ __forceinline__ float tanha(float x) {
    float y;
    asm("tanh.approx.f32 %0, %1;" : "=f"(y) : "f"(x));
    return y;
}
__device__ __forceinline__ float sigm(float x) { return fmaf(tanha(0.5f * x), 0.5f, 0.5f); }

__device__ __forceinline__ uint32_t f2h2(float lo, float hi) {
    __half2 h = __floats2half2_rn(lo, hi);
    return *reinterpret_cast<uint32_t*>(&h);
}

__device__ __forceinline__ void mma16(float* d, uint4 a, uint32_t b0, uint32_t b1) {
    asm volatile(
        "mma.sync.aligned.m16n8k16.row.col.f32.f16.f16.f32 "
        "{%0,%1,%2,%3},{%4,%5,%6,%7},{%8,%9},{%0,%1,%2,%3};\n"
        : "+f"(d[0]), "+f"(d[1]), "+f"(d[2]), "+f"(d[3])
        : "r"(a.x), "r"(a.y), "r"(a.z), "r"(a.w), "r"(b0), "r"(b1));
}

__device__ __forceinline__ void waitflag(const unsigned* p, unsigned tgt) {
    unsigned v;
    do {
        asm volatile("ld.acquire.gpu.global.u32 %0, [%1];" : "=r"(v) : "l"(p) : "memory");
    } while (v < tgt);
}
__device__ __forceinline__ void waitflag4(const FlagG* f, unsigned tgt) {
    unsigned a, b, c, d;
    do {
        asm volatile("ld.acquire.gpu.global.u32 %0, [%1];" : "=r"(a) : "l"(&f->g[0]) : "memory");
        asm volatile("ld.acquire.gpu.global.u32 %0, [%1];" : "=r"(b) : "l"(&f->g[1]) : "memory");
        asm volatile("ld.acquire.gpu.global.u32 %0, [%1];" : "=r"(c) : "l"(&f->g[2]) : "memory");
        asm volatile("ld.acquire.gpu.global.u32 %0, [%1];" : "=r"(d) : "l"(&f->g[3]) : "memory");
    } while (a < tgt || b < tgt || c < tgt || d < tgt);
}

// 8 k16-tiles, TWO m16 tiles per warp: per kt: 2 LDG.128 (A) + 2 LDS.128 (B) + 8 MMA.
__device__ __forceinline__ void gemm8x2(float acc[2][4][4], const uint4* __restrict__ Ap,
                                        const uint4* __restrict__ Bp) {
    uint4 a0[4], a1[4];
#pragma unroll
    for (int i = 0; i < 4; i++) {
        a0[i] = __ldcg(Ap + i * 128);
        a1[i] = __ldcg(Ap + i * 128 + 32);
    }
#pragma unroll
    for (int i = 0; i < 8; i++) {
        uint4 av0 = a0[i & 3], av1 = a1[i & 3];
        uint4 q1 = Bp[i * 64];
        uint4 q2 = Bp[i * 64 + 32];
        if (i < 4) {
            a0[i & 3] = __ldcg(Ap + (i + 4) * 128);
            a1[i & 3] = __ldcg(Ap + (i + 4) * 128 + 32);
        }
        mma16(acc[0][0], av0, q1.x, q1.y);
        mma16(acc[0][1], av0, q1.z, q1.w);
        mma16(acc[0][2], av0, q2.x, q2.y);
        mma16(acc[0][3], av0, q2.z, q2.w);
        mma16(acc[1][0], av1, q1.x, q1.y);
        mma16(acc[1][1], av1, q1.z, q1.w);
        mma16(acc[1][2], av1, q2.x, q2.y);
        mma16(acc[1][3], av1, q2.z, q2.w);
    }
}

// ---------------- setup kernels ----------------
__global__ void reset_kernel() {
    int idx = blockIdx.x * 256 + threadIdx.x;
    if (idx < TT + 2) {
#pragma unroll
        for (int j = 0; j < 4; j++) {
            g_f1[idx].g[j] = (idx == 0) ? 16u : 0u;
            g_f2[idx].g[j] = (idx == 0) ? 16u : 0u;
        }
    }
    if (idx < 16384) {
        g_h1s[3 * 16384 + idx] = 0u;   // h1[-1] slab ((-1)&3 = 3)
        g_h2s[16384 + idx] = 0u;       // h2[-1] slab ((-1)&1 = 1)
    }
}

__global__ void pack_kernel(const float* __restrict__ Whh0, const float* __restrict__ Wih0,
                            const float* __restrict__ Wih1, const float* __restrict__ Whh1,
                            const float* __restrict__ bih0, const float* __restrict__ bhh0,
                            const float* __restrict__ bih1, const float* __restrict__ bhh1) {
    int cb = blockIdx.x;
    if (cb < 64) {
        int c = cb;
        uint32_t* dst = g_wf1 + c * 8192;
        for (int idx = threadIdx.x; idx < 8192; idx += 256) {
            int e = idx & 3, lane = (idx >> 2) & 31, p = (idx >> 7) & 1, kt = idx >> 8;
            int gid = lane >> 2, tig = lane & 3;
            int nt = 2 * p + (e >> 1);
            int gate = (nt & 1) * 2 + (gid & 1);
            int u = c * 8 + (nt >> 1) * 4 + (gid >> 1);
            int row = gate * 512 + u;
            int k = kt * 16 + (e & 1) * 8 + tig * 2;
            dst[idx] = f2h2(Whh0[row * HH + k], Whh0[row * HH + k + 1]);
        }
        // W_ih0 B-frags (same layout, kt 0..2, K padded 36->48 with zeros)
        uint32_t* dx = g_wfx + c * 768;
        for (int idx = threadIdx.x; idx < 768; idx += 256) {
            int e = idx & 3, lane = (idx >> 2) & 31, p = (idx >> 7) & 1, kt = idx >> 8;
            int gid = lane >> 2, tig = lane & 3;
            int nt = 2 * p + (e >> 1);
            int gate = (nt & 1) * 2 + (gid & 1);
            int u = c * 8 + (nt >> 1) * 4 + (gid >> 1);
            int row = gate * 512 + u;
            int k = kt * 16 + (e & 1) * 8 + tig * 2;
            float v0 = (k < FF) ? Wih0[row * FF + k] : 0.f;
            float v1 = (k + 1 < FF) ? Wih0[row * FF + k + 1] : 0.f;
            dx[idx] = f2h2(v0, v1);
        }
        // layer1 bias rows [rl32]: rl = gate*8 + uloc
        if (threadIdx.x < 32) {
            int rl = threadIdx.x;
            int row = (rl >> 3) * 512 + c * 8 + (rl & 7);
            g_b1p[c * 32 + rl] = bih0[row] + bhh0[row];
        }
    } else {
        int c = cb - 64;
        uint32_t* dst = g_wf2 + c * 16384;
        for (int idx = threadIdx.x; idx < 16384; idx += 256) {
            int e = idx & 3, lane = (idx >> 2) & 31, p = (idx >> 7) & 1, kt = idx >> 8;
            int gid = lane >> 2, tig = lane & 3;
            int nt = 2 * p + (e >> 1);
            int gate = (nt & 1) * 2 + (gid & 1);
            int u = c * 8 + (nt >> 1) * 4 + (gid >> 1);
            int row = gate * 512 + u;
            float v0, v1;
            if (kt < 32) {
                int k = kt * 16 + (e & 1) * 8 + tig * 2;
                v0 = Wih1[row * HH + k]; v1 = Wih1[row * HH + k + 1];
            } else {
                int k = (kt - 32) * 16 + (e & 1) * 8 + tig * 2;
                v0 = Whh1[row * HH + k]; v1 = Whh1[row * HH + k + 1];
            }
            dst[idx] = f2h2(v0, v1);
        }
        // bias in acc-slot layout: [tl128][q4][e4]; gate=(q&1)*2+(e&1); u=c*8+(q>>1)*4+tig
        for (int idx = threadIdx.x; idx < 2048; idx += 256) {
            int e = idx & 3, q = (idx >> 2) & 3, tl = idx >> 4;
            int tig = tl & 3;
            int u = c * 8 + (q >> 1) * 4 + tig;
            int gate = (q & 1) * 2 + (e & 1);
            int row = gate * 512 + u;
            g_b2p[c * 2048 + idx] = bih1[row] + bhh1[row];
        }
    }
}

// x -> fp16 A-fragments. 384 threads = (kt3, mt4, lane32); one uint4 per thread per t.
__global__ void xpack_kernel(const float* __restrict__ x) {
    int t = blockIdx.x;
    int tid = threadIdx.x;
    int kt = tid >> 7, rem = tid & 127;
    int mt = rem >> 5, lane = rem & 31;
    int gid = lane >> 2, tig = lane & 3;
    uint32_t r[4];
#pragma unroll
    for (int reg = 0; reg < 4; reg++) {
        int b = mt * 16 + gid + 8 * (reg & 1);
        int k = kt * 16 + (reg >> 1) * 8 + tig * 2;
        float v0 = (k < FF) ? x[((size_t)b * TT + t) * FF + k] : 0.f;
        float v1 = (k + 1 < FF) ? x[((size_t)b * TT + t) * FF + k + 1] : 0.f;
        r[reg] = f2h2(v0, v1);
    }
    uint4* op = (uint4*)g_xf + (size_t)t * 384 + (kt * 4 + mt) * 32 + lane;
    *op = make_uint4(r[0], r[1], r[2], r[3]);
}

// tensor-core xg0: block = (c, 8-t chunk); warp = one t, all 4 mt, n32, K=48 (3 kt).
__global__ void xg0tc_kernel() {
    __shared__ uint4 Ws4[192];     // 768 uint32 W_ih0 frags for this c
    __shared__ float bsm[32];
    int c = blockIdx.x & 63, t0 = (blockIdx.x >> 6) * 8;
    int tid = threadIdx.x;
    for (int i = tid; i < 192; i += 256) Ws4[i] = ((const uint4*)(g_wfx + c * 768))[i];
    if (tid < 32) bsm[tid] = g_b1p[c * 32 + tid];
    __syncthreads();
    int w = tid >> 5, lane = tid & 31, tig = lane & 3;
    int t = t0 + w;
    if (t >= TT) return;
    float acc[4][4][4];
#pragma unroll
    for (int mt = 0; mt < 4; mt++)
#pragma unroll
        for (int q = 0; q < 4; q++)
#pragma unroll
            for (int e = 0; e < 4; e++)
                acc[mt][q][e] = bsm[((q & 1) * 2 + (e & 1)) * 8 + (q >> 1) * 4 + tig];
    const uint4* Af = (const uint4*)g_xf + (size_t)t * 384;
#pragma unroll
    for (int kt = 0; kt < 3; kt++) {
        uint4 a[4];
#pragma unroll
        for (int mt = 0; mt < 4; mt++) a[mt] = __ldg(Af + (kt * 4 + mt) * 32 + lane);
        uint4 q1 = Ws4[kt * 64 + lane];
        uint4 q2 = Ws4[kt * 64 + 32 + lane];
#pragma unroll
        for (int mt = 0; mt < 4; mt++) {
            mma16(acc[mt][0], a[mt], q1.x, q1.y);
            mma16(acc[mt][1], a[mt], q1.z, q1.w);
            mma16(acc[mt][2], a[mt], q2.x, q2.y);
            mma16(acc[mt][3], a[mt], q2.z, q2.w);
        }
    }
#pragma unroll
    for (int mt = 0; mt < 4; mt++) {
        int tl = mt * 32 + lane;
        uint4 o0, o1;
        o0.x = f2h2(acc[mt][0][0], acc[mt][0][1]); o0.y = f2h2(acc[mt][0][2], acc[mt][0][3]);
        o0.z = f2h2(acc[mt][1][0], acc[mt][1][1]); o0.w = f2h2(acc[mt][1][2], acc[mt][1][3]);
        o1.x = f2h2(acc[mt][2][0], acc[mt][2][1]); o1.y = f2h2(acc[mt][2][2], acc[mt][2][3]);
        o1.z = f2h2(acc[mt][3][0], acc[mt][3][1]); o1.w = f2h2(acc[mt][3][2], acc[mt][3][3]);
        uint4* op = (uint4*)(g_xg0ph + (size_t)t * 65536 + c * 1024 + tl * 8);
        op[0] = o0; op[1] = o1;
    }
}

// ---------------- persistent 2-layer LSTM (unchanged from R14 best) ----------------
// smem: Bs uint4[4096] (64KB weights) + EX float4[2048] (32KB 4-way reduction)
#define SMEM_BYTES 98304

__global__ void __launch_bounds__(NT, 1) lstm_kernel() {
    extern __shared__ uint4 smemu[];
    uint4* Bs = smemu;
    float4* EX = (float4*)(smemu + 4096);

    const int cta = blockIdx.x;
    const int layer = cta >> 6;
    const int c = cta & 63;
    const int tid = threadIdx.x;
    const int w = tid >> 5;
    const int kq = w & 3;                  // k-quarter (= producer flag group for A reads)
    const int mh = w >> 2;                 // m-half (m32)
    const int lane = tid & 31;
    const int gid = lane >> 2, tig = lane & 3;
    const int P = kq >> 1;                 // owned nt-pair (uu-half)
    const int mI = kq & 1;                 // owned m-tile within the warp's m32
    const int mtS = mh * 2 + mI;           // owned global m16 tile
    const int tlo = mtS * 32 + lane;       // owner slot in [tl128] layouts

    {   // weights -> smem
        const uint4* wsrc = (const uint4*)(layer ? (g_wf2 + c * 16384) : (g_wf1 + c * 8192));
        int tot = layer ? 4096 : 2048;
        for (int i = tid; i < tot; i += NT) Bs[i] = wsrc[i];
    }
    float bias8[8];
    if (layer) {
        const float4* bp = (const float4*)(g_b2p + c * 2048 + tlo * 16 + P * 8);
        float4 v0 = bp[0], v1 = bp[1];
        bias8[0] = v0.x; bias8[1] = v0.y; bias8[2] = v0.z; bias8[3] = v0.w;
        bias8[4] = v1.x; bias8[5] = v1.y; bias8[6] = v1.z; bias8[7] = v1.w;
    }
    float cst[2] = {0.f, 0.f};             // 2 owned cells (batches bb=0,1)
    __syncthreads();

    const int ktS = c >> 1;
    const int sbase = ((ktS * 4 + mtS) * 32 + gid * 4 + P * 2 + (tig >> 1)) * 4 + 2 * (c & 1);
    const int hpar = tig & 1;
    const int myGrp = c >> 4;

    for (int t = 0; t < TT; t++) {
        float acc[2][4][4];
#pragma unroll
        for (int i = 0; i < 32; i++) acc[i >> 4][(i >> 2) & 3][i & 3] = 0.f;
        uint4 xg;
        if (!layer) {
            // owner prefetch of fp16 acc-init (one uint4); folded after reduction
            xg = __ldcg((const uint4*)(g_xg0ph + (size_t)t * 65536 + c * 1024 + tlo * 8 + P * 4));
            const uint4* Ap = (const uint4*)(g_h1s + ((t - 1) & 3) * 16384) + kq * 1024 + mh * 64 + lane;
            waitflag(&g_f1[t].g[kq], 16);              // exactly this warp's kt range
            gemm8x2(acc, Ap, Bs + kq * 512 + lane);
            if (t >= 4) waitflag4(&g_f2[t - 3], 16);   // ring guard, off the front
        } else {
            const uint4* Ap1 = (const uint4*)(g_h1s + (t & 3) * 16384) + kq * 1024 + mh * 64 + lane;
            waitflag(&g_f1[t + 1].g[kq], 16);          // h1[t] (layer1 runs ahead)
            gemm8x2(acc, Ap1, Bs + kq * 512 + lane);   // W_ih1 quarter
            const uint4* Ap2 = (const uint4*)(g_h2s + ((t - 1) & 1) * 16384) + kq * 1024 + mh * 64 + lane;
            waitflag(&g_f2[t].g[kq], 16);              // h2[t-1] — serial dep
            gemm8x2(acc, Ap2, Bs + 2048 + kq * 512 + lane);  // W_hh1 quarter
        }
        // ship the 3 unowned (mi, nt-pair) chunks
#pragma unroll
        for (int mi = 0; mi < 2; mi++) {
#pragma unroll
            for (int p = 0; p < 2; p++) {
                if (mi == mI && p == P) continue;      // keep own chunk in regs
                int oidx = ((((mh * 2 + mi) * 2 + p) * 4 + kq) * 32 + lane) * 2;
                EX[oidx]     = make_float4(acc[mi][p * 2][0], acc[mi][p * 2][1],
                                           acc[mi][p * 2][2], acc[mi][p * 2][3]);
                EX[oidx + 1] = make_float4(acc[mi][p * 2 + 1][0], acc[mi][p * 2 + 1][1],
                                           acc[mi][p * 2 + 1][2], acc[mi][p * 2 + 1][3]);
            }
        }
        __syncthreads();
        {
            float v[8];
#pragma unroll
            for (int e = 0; e < 4; e++) { v[e] = acc[mI][P * 2][e]; v[4 + e] = acc[mI][P * 2 + 1][e]; }
#pragma unroll
            for (int src = 0; src < 4; src++) {
                if (src == kq) continue;
                int iidx = (((mtS * 2 + P) * 4 + src) * 32 + lane) * 2;
                float4 fa = EX[iidx], fb = EX[iidx + 1];
                v[0] += fa.x; v[1] += fa.y; v[2] += fa.z; v[3] += fa.w;
                v[4] += fb.x; v[5] += fb.y; v[6] += fb.z; v[7] += fb.w;
            }
            if (!layer) {
                const __half2* hx = (const __half2*)&xg;
#pragma unroll
                for (int k = 0; k < 4; k++) {
                    float2 p2 = __half22float2(hx[k]);
                    v[k * 2] += p2.x; v[k * 2 + 1] += p2.y;
                }
            } else {
#pragma unroll
                for (int k = 0; k < 8; k++) v[k] += bias8[k];
            }
            uint32_t* slab = layer ? (g_h2s + (t & 1) * 16384) : (g_h1s + (t & 3) * 16384);
            uint16_t* hp = (uint16_t*)slab;
#pragma unroll
            for (int bb = 0; bb < 2; bb++) {
                float iv = sigm(v[bb * 2]);
                float fv = sigm(v[bb * 2 + 1]);
                float gv = tanha(v[4 + bb * 2]);
                float ov = sigm(v[4 + bb * 2 + 1]);
                float cv = fmaf(fv, cst[bb], iv * gv);
                cst[bb] = cv;
                float hv = ov * tanha(cv);
                __half hh = __float2half_rn(hv);
                hp[(sbase + bb) * 2 + hpar] = __half_as_ushort(hh);
            }
        }
        __syncthreads();   // h-stores + EX reuse guard
        if (tid == 0) {
            unsigned* fp = layer ? &g_f2[t + 1].g[myGrp] : &g_f1[t + 1].g[myGrp];
            asm volatile("red.release.gpu.global.add.u32 [%0], 1;" ::"l"(fp) : "memory");
        }
    }
}

// ---------------- final projection ----------------
__global__ void out_kernel(const float* __restrict__ Wout, const float* __restrict__ bout,
                           float* __restrict__ out) {
    __shared__ float hs[512];
    int b = blockIdx.x;
    const uint32_t* slab = g_h2s + ((TT - 1) & 1) * 16384;
    for (int k = threadIdx.x; k < 512; k += 64) {
        int kt = k >> 4, ku = k & 15, mtb = b >> 4, r = b & 15;
        int laneS = (r & 7) * 4 + ((ku & 7) >> 1);
        int reg = (r >> 3) + 2 * (ku >> 3);
        uint32_t v = slab[((kt * 4 + mtb) * 32 + laneS) * 4 + reg];
        __half2 h2v = *reinterpret_cast<__half2*>(&v);
        hs[k] = (ku & 1) ? __high2float(h2v) : __low2float(h2v);
    }
    __syncthreads();
    int o = threadIdx.x;
    float acc = bout[o];
    const float* wr = Wout + o * HH;
#pragma unroll 8
    for (int k = 0; k < HH; k++) acc = fmaf(hs[k], wr[k], acc);
    out[b * 64 + o] = acc;
}

// ---------------- launch ----------------
extern "C" void kernel_launch(void* const* d_in, const int* in_sizes, int n_in,
                              void* d_out, int out_size) {
    const float* x    = (const float*)d_in[0];
    const float* Wih0 = (const float*)d_in[1];
    const float* Whh0 = (const float*)d_in[2];
    const float* bih0 = (const float*)d_in[3];
    const float* bhh0 = (const float*)d_in[4];
    const float* Wih1 = (const float*)d_in[5];
    const float* Whh1 = (const float*)d_in[6];
    const float* bih1 = (const float*)d_in[7];
    const float* bhh1 = (const float*)d_in[8];
    const float* Wout = (const float*)d_in[9];
    const float* bout = (const float*)d_in[10];
    float* out = (float*)d_out;

    cudaFuncSetAttribute(lstm_kernel, cudaFuncAttributeMaxDynamicSharedMemorySize, SMEM_BYTES);

    reset_kernel<<<64, 256>>>();
    pack_kernel<<<128, 256>>>(Whh0, Wih0, Wih1, Whh1, bih0, bhh0, bih1, bhh1);
    xpack_kernel<<<TT, 384>>>(x);
    xg0tc_kernel<<<((TT + 7) / 8) * 64, 256>>>();
    lstm_kernel<<<GRID, NT, SMEM_BYTES>>>();
    out_kernel<<<64, 64>>>(Wout, bout, out);
}

// round 16
// speedup vs baseline: 1.3605x; 1.0143x over previous
#include <cuda_runtime.h>
#include <cuda_fp16.h>
#include <cstdint>

#define BB 64
#define TT 1500
#define FF 36
#define HH 512
#define NT 256          // 8 warps: kq4 x mh2; each warp m32 x n32
#define GRID 128        // 64 CTAs per layer, 8 units per CTA

// ---------------- device globals ----------------
__device__ uint32_t g_xg0ph[(size_t)TT * 65536];  // 393MB fp16 acc-init [t][c64][tl128][16h]
__device__ uint32_t g_xf[(size_t)TT * 1536];      // 9.2MB x fp16 A-frags [t][kt3][mt4][lane32][reg4]
__device__ float g_b2p[64 * 2048];                // layer2 bias  [c][tl128][q4][e4]
__device__ float g_b1p[64 * 32];                  // layer1 bias rows [c][rl32]
__device__ uint32_t g_wf1[64 * 8192];             // layer1 B-frags [c][kt32][p2][lane32][e4]
__device__ uint32_t g_wf2[64 * 16384];            // layer2 B-frags [c][kt64][p2][lane32][e4]
__device__ uint32_t g_wfx[64 * 768];              // W_ih0 B-frags [c][kt3][p2][lane32][e4] (K pad 48)
__device__ uint32_t g_h1s[4 * 16384];             // h1 ring, fp16 A-frag layout
__device__ uint32_t g_h2s[2 * 16384];             // h2 ring
struct alignas(128) FlagG { unsigned g[4]; unsigned pad[28]; };
__device__ FlagG g_f1[TT + 2];
__device__ FlagG g_f2[TT + 2];

// ---------------- helpers ----------------
__device__ __forceinline__ float tanha(float x) {
    float y;
    asm("tanh.approx.f32 %0, %1;" : "=f"(y) : "f"(x));
    return y;
}
__device__ __forceinline__ float sigm(float x) { return fmaf(tanha(0.5f * x), 0.5f, 0.5f); }

__device__ __forceinline__ uint32_t f2h2(float lo, float hi) {
    __half2 h = __floats2half2_rn(lo, hi);
    return *reinterpret_cast<uint32_t*>(&h);
}

__device__ __forceinline__ void mma16(float* d, uint4 a, uint32_t b0, uint32_t b1) {
    asm volatile(
        "mma.sync.aligned.m16n8k16.row.col.f32.f16.f16.f32 "
        "{%0,%1,%2,%3},{%4,%5,%6,%7},{%8,%9},{%0,%1,%2,%3};\n"
        : "+f"(d[0]), "+f"(d[1]), "+f"(d[2]), "+f"(d[3])
        : "r"(a.x), "r"(a.y), "r"(a.z), "r"(a.w), "r"(b0), "r"(b1));
}

__device__ __forceinline__ void waitflag(const unsigned* p, unsigned tgt) {
    unsigned v;
    do {
        asm volatile("ld.acquire.gpu.global.u32 %0, [%1];" : "=r"(v) : "l"(p) : "memory");
    } while (v < tgt);
}
__device__ __forceinline__ void waitflag4(const FlagG* f, unsigned tgt) {
    unsigned a, b, c, d;
    do {
        asm volatile("ld.acquire.gpu.global.u32 %0, [%1];" : "=r"(a) : "l"(&f->g[0]) : "memory");
        asm volatile("ld.acquire.gpu.global.u32 %0, [%1];" : "=r"(b) : "l"(&f->g[1]) : "memory");
        asm volatile("ld.acquire.gpu.global.u32 %0, [%1];" : "=r"(c) : "l"(&f->g[2]) : "memory");
        asm volatile("ld.acquire.gpu.global.u32 %0, [%1];" : "=r"(d) : "l"(&f->g[3]) : "memory");
    } while (a < tgt || b < tgt || c < tgt || d < tgt);
}

// 8 k16-tiles, TWO m16 tiles per warp, B from SMEM: per kt: 2 LDG + 2 LDS + 8 MMA.
__device__ __forceinline__ void gemm8x2(float acc[2][4][4], const uint4* __restrict__ Ap,
                                        const uint4* __restrict__ Bp) {
    uint4 a0[4], a1[4];
#pragma unroll
    for (int i = 0; i < 4; i++) {
        a0[i] = __ldcg(Ap + i * 128);
        a1[i] = __ldcg(Ap + i * 128 + 32);
    }
#pragma unroll
    for (int i = 0; i < 8; i++) {
        uint4 av0 = a0[i & 3], av1 = a1[i & 3];
        uint4 q1 = Bp[i * 64];
        uint4 q2 = Bp[i * 64 + 32];
        if (i < 4) {
            a0[i & 3] = __ldcg(Ap + (i + 4) * 128);
            a1[i & 3] = __ldcg(Ap + (i + 4) * 128 + 32);
        }
        mma16(acc[0][0], av0, q1.x, q1.y);
        mma16(acc[0][1], av0, q1.z, q1.w);
        mma16(acc[0][2], av0, q2.x, q2.y);
        mma16(acc[0][3], av0, q2.z, q2.w);
        mma16(acc[1][0], av1, q1.x, q1.y);
        mma16(acc[1][1], av1, q1.z, q1.w);
        mma16(acc[1][2], av1, q2.x, q2.y);
        mma16(acc[1][3], av1, q2.z, q2.w);
    }
}

// Same, but B fragments live in REGISTERS (weights constant across steps): per kt: 2 LDG + 8 MMA.
__device__ __forceinline__ void gemm8x2_regB(float acc[2][4][4], const uint4* __restrict__ Ap,
                                             const uint4 bq1[8], const uint4 bq2[8]) {
    uint4 a0[4], a1[4];
#pragma unroll
    for (int i = 0; i < 4; i++) {
        a0[i] = __ldcg(Ap + i * 128);
        a1[i] = __ldcg(Ap + i * 128 + 32);
    }
#pragma unroll
    for (int i = 0; i < 8; i++) {
        uint4 av0 = a0[i & 3], av1 = a1[i & 3];
        if (i < 4) {
            a0[i & 3] = __ldcg(Ap + (i + 4) * 128);
            a1[i & 3] = __ldcg(Ap + (i + 4) * 128 + 32);
        }
        mma16(acc[0][0], av0, bq1[i].x, bq1[i].y);
        mma16(acc[0][1], av0, bq1[i].z, bq1[i].w);
        mma16(acc[0][2], av0, bq2[i].x, bq2[i].y);
        mma16(acc[0][3], av0, bq2[i].z, bq2[i].w);
        mma16(acc[1][0], av1, bq1[i].x, bq1[i].y);
        mma16(acc[1][1], av1, bq1[i].z, bq1[i].w);
        mma16(acc[1][2], av1, bq2[i].x, bq2[i].y);
        mma16(acc[1][3], av1, bq2[i].z, bq2[i].w);
    }
}

// ---------------- setup kernels ----------------
__global__ void reset_kernel() {
    int idx = blockIdx.x * 256 + threadIdx.x;
    if (idx < TT + 2) {
#pragma unroll
        for (int j = 0; j < 4; j++) {
            g_f1[idx].g[j] = (idx == 0) ? 16u : 0u;
            g_f2[idx].g[j] = (idx == 0) ? 16u : 0u;
        }
    }
    if (idx < 16384) {
        g_h1s[3 * 16384 + idx] = 0u;   // h1[-1] slab ((-1)&3 = 3)
        g_h2s[16384 + idx] = 0u;       // h2[-1] slab ((-1)&1 = 1)
    }
}

__global__ void pack_kernel(const float* __restrict__ Whh0, const float* __restrict__ Wih0,
                            const float* __restrict__ Wih1, const float* __restrict__ Whh1,
                            const float* __restrict__ bih0, const float* __restrict__ bhh0,
                            const float* __restrict__ bih1, const float* __restrict__ bhh1) {
    int cb = blockIdx.x;
    if (cb < 64) {
        int c = cb;
        uint32_t* dst = g_wf1 + c * 8192;
        for (int idx = threadIdx.x; idx < 8192; idx += 256) {
            int e = idx & 3, lane = (idx >> 2) & 31, p = (idx >> 7) & 1, kt = idx >> 8;
            int gid = lane >> 2, tig = lane & 3;
            int nt = 2 * p + (e >> 1);
            int gate = (nt & 1) * 2 + (gid & 1);
            int u = c * 8 + (nt >> 1) * 4 + (gid >> 1);
            int row = gate * 512 + u;
            int k = kt * 16 + (e & 1) * 8 + tig * 2;
            dst[idx] = f2h2(Whh0[row * HH + k], Whh0[row * HH + k + 1]);
        }
        // W_ih0 B-frags (same layout, kt 0..2, K padded 36->48 with zeros)
        uint32_t* dx = g_wfx + c * 768;
        for (int idx = threadIdx.x; idx < 768; idx += 256) {
            int e = idx & 3, lane = (idx >> 2) & 31, p = (idx >> 7) & 1, kt = idx >> 8;
            int gid = lane >> 2, tig = lane & 3;
            int nt = 2 * p + (e >> 1);
            int gate = (nt & 1) * 2 + (gid & 1);
            int u = c * 8 + (nt >> 1) * 4 + (gid >> 1);
            int row = gate * 512 + u;
            int k = kt * 16 + (e & 1) * 8 + tig * 2;
            float v0 = (k < FF) ? Wih0[row * FF + k] : 0.f;
            float v1 = (k + 1 < FF) ? Wih0[row * FF + k + 1] : 0.f;
            dx[idx] = f2h2(v0, v1);
        }
        if (threadIdx.x < 32) {
            int rl = threadIdx.x;
            int row = (rl >> 3) * 512 + c * 8 + (rl & 7);
            g_b1p[c * 32 + rl] = bih0[row] + bhh0[row];
        }
    } else {
        int c = cb - 64;
        uint32_t* dst = g_wf2 + c * 16384;
        for (int idx = threadIdx.x; idx < 16384; idx += 256) {
            int e = idx & 3, lane = (idx >> 2) & 31, p = (idx >> 7) & 1, kt = idx >> 8;
            int gid = lane >> 2, tig = lane & 3;
            int nt = 2 * p + (e >> 1);
            int gate = (nt & 1) * 2 + (gid & 1);
            int u = c * 8 + (nt >> 1) * 4 + (gid >> 1);
            int row = gate * 512 + u;
            float v0, v1;
            if (kt < 32) {
                int k = kt * 16 + (e & 1) * 8 + tig * 2;
                v0 = Wih1[row * HH + k]; v1 = Wih1[row * HH + k + 1];
            } else {
                int k = (kt - 32) * 16 + (e & 1) * 8 + tig * 2;
                v0 = Whh1[row * HH + k]; v1 = Whh1[row * HH + k + 1];
            }
            dst[idx] = f2h2(v0, v1);
        }
        // bias in acc-slot layout: [tl128][q4][e4]; gate=(q&1)*2+(e&1); u=c*8+(q>>1)*4+tig
        for (int idx = threadIdx.x; idx < 2048; idx += 256) {
            int e = idx & 3, q = (idx >> 2) & 3, tl = idx >> 4;
            int tig = tl & 3;
            int u = c * 8 + (q >> 1) * 4 + tig;
            int gate = (q & 1) * 2 + (e & 1);
            int row = gate * 512 + u;
            g_b2p[c * 2048 + idx] = bih1[row] + bhh1[row];
        }
    }
}

// x -> fp16 A-fragments. 384 threads = (kt3, mt4, lane32); one uint4 per thread per t.
__global__ void xpack_kernel(const float* __restrict__ x) {
    int t = blockIdx.x;
    int tid = threadIdx.x;
    int kt = tid >> 7, rem = tid & 127;
    int mt = rem >> 5, lane = rem & 31;
    int gid = lane >> 2, tig = lane & 3;
    uint32_t r[4];
#pragma unroll
    for (int reg = 0; reg < 4; reg++) {
        int b = mt * 16 + gid + 8 * (reg & 1);
        int k = kt * 16 + (reg >> 1) * 8 + tig * 2;
        float v0 = (k < FF) ? x[((size_t)b * TT + t) * FF + k] : 0.f;
        float v1 = (k + 1 < FF) ? x[((size_t)b * TT + t) * FF + k + 1] : 0.f;
        r[reg] = f2h2(v0, v1);
    }
    uint4* op = (uint4*)g_xf + (size_t)t * 384 + (kt * 4 + mt) * 32 + lane;
    *op = make_uint4(r[0], r[1], r[2], r[3]);
}

// tensor-core xg0: block = (c, 8-t chunk); warp = one t, all 4 mt, n32, K=48 (3 kt).
__global__ void xg0tc_kernel() {
    __shared__ uint4 Ws4[192];
    __shared__ float bsm[32];
    int c = blockIdx.x & 63, t0 = (blockIdx.x >> 6) * 8;
    int tid = threadIdx.x;
    for (int i = tid; i < 192; i += 256) Ws4[i] = ((const uint4*)(g_wfx + c * 768))[i];
    if (tid < 32) bsm[tid] = g_b1p[c * 32 + tid];
    __syncthreads();
    int w = tid >> 5, lane = tid & 31, tig = lane & 3;
    int t = t0 + w;
    if (t >= TT) return;
    float acc[4][4][4];
#pragma unroll
    for (int mt = 0; mt < 4; mt++)
#pragma unroll
        for (int q = 0; q < 4; q++)
#pragma unroll
            for (int e = 0; e < 4; e++)
                acc[mt][q][e] = bsm[((q & 1) * 2 + (e & 1)) * 8 + (q >> 1) * 4 + tig];
    const uint4* Af = (const uint4*)g_xf + (size_t)t * 384;
#pragma unroll
    for (int kt = 0; kt < 3; kt++) {
        uint4 a[4];
#pragma unroll
        for (int mt = 0; mt < 4; mt++) a[mt] = __ldg(Af + (kt * 4 + mt) * 32 + lane);
        uint4 q1 = Ws4[kt * 64 + lane];
        uint4 q2 = Ws4[kt * 64 + 32 + lane];
#pragma unroll
        for (int mt = 0; mt < 4; mt++) {
            mma16(acc[mt][0], a[mt], q1.x, q1.y);
            mma16(acc[mt][1], a[mt], q1.z, q1.w);
            mma16(acc[mt][2], a[mt], q2.x, q2.y);
            mma16(acc[mt][3], a[mt], q2.z, q2.w);
        }
    }
#pragma unroll
    for (int mt = 0; mt < 4; mt++) {
        int tl = mt * 32 + lane;
        uint4 o0, o1;
        o0.x = f2h2(acc[mt][0][0], acc[mt][0][1]); o0.y = f2h2(acc[mt][0][2], acc[mt][0][3]);
        o0.z = f2h2(acc[mt][1][0], acc[mt][1][1]); o0.w = f2h2(acc[mt][1][2], acc[mt][1][3]);
        o1.x = f2h2(acc[mt][2][0], acc[mt][2][1]); o1.y = f2h2(acc[mt][2][2], acc[mt][2][3]);
        o1.z = f2h2(acc[mt][3][0], acc[mt][3][1]); o1.w = f2h2(acc[mt][3][2], acc[mt][3][3]);
        uint4* op = (uint4*)(g_xg0ph + (size_t)t * 65536 + c * 1024 + tl * 8);
        op[0] = o0; op[1] = o1;
    }
}

// ---------------- persistent 2-layer LSTM ----------------
// smem: Bs uint4[2048] (32KB, layer2 W_ih1 only) + EX float4[2048] (32KB reduction)
#define SMEM_BYTES 65536

__global__ void __launch_bounds__(NT, 1) lstm_kernel() {
    extern __shared__ uint4 smemu[];
    uint4* Bs = smemu;
    float4* EX = (float4*)(smemu + 2048);

    const int cta = blockIdx.x;
    const int layer = cta >> 6;
    const int c = cta & 63;
    const int tid = threadIdx.x;
    const int w = tid >> 5;
    const int kq = w & 3;                  // k-quarter (= producer flag group for A reads)
    const int mh = w >> 2;                 // m-half (m32)
    const int lane = tid & 31;
    const int gid = lane >> 2, tig = lane & 3;
    const int P = kq >> 1;                 // owned nt-pair (uu-half)
    const int mI = kq & 1;                 // owned m-tile within the warp's m32
    const int mtS = mh * 2 + mI;           // owned global m16 tile
    const int tlo = mtS * 32 + lane;       // owner slot in [tl128] layouts

    // serial-path B fragments -> REGISTERS (layer1: its only gemm; layer2: W_hh1)
    uint4 bq1[8], bq2[8];
    {
        const uint4* wb = layer ? ((const uint4*)g_wf2) + c * 4096 + 2048 + kq * 512
                                : ((const uint4*)g_wf1) + c * 2048 + kq * 512;
#pragma unroll
        for (int i = 0; i < 8; i++) {
            bq1[i] = wb[i * 64 + lane];
            bq2[i] = wb[i * 64 + 32 + lane];
        }
    }
    // layer2 only: W_ih1 half -> smem (off-critical-path gemm keeps smem B)
    if (layer) {
        const uint4* wsrc = (const uint4*)(g_wf2 + c * 16384);
        for (int i = tid; i < 2048; i += NT) Bs[i] = wsrc[i];
    }
    float bias8[8];
    if (layer) {
        const float4* bp = (const float4*)(g_b2p + c * 2048 + tlo * 16 + P * 8);
        float4 v0 = bp[0], v1 = bp[1];
        bias8[0] = v0.x; bias8[1] = v0.y; bias8[2] = v0.z; bias8[3] = v0.w;
        bias8[4] = v1.x; bias8[5] = v1.y; bias8[6] = v1.z; bias8[7] = v1.w;
    }
    float cst[2] = {0.f, 0.f};             // 2 owned cells (batches bb=0,1)
    __syncthreads();

    const int ktS = c >> 1;
    const int sbase = ((ktS * 4 + mtS) * 32 + gid * 4 + P * 2 + (tig >> 1)) * 4 + 2 * (c & 1);
    const int hpar = tig & 1;
    const int myGrp = c >> 4;

    for (int t = 0; t < TT; t++) {
        float acc[2][4][4];
#pragma unroll
        for (int i = 0; i < 32; i++) acc[i >> 4][(i >> 2) & 3][i & 3] = 0.f;
        uint4 xg;
        if (!layer) {
            // owner prefetch of fp16 acc-init (one uint4); folded after reduction
            xg = __ldcg((const uint4*)(g_xg0ph + (size_t)t * 65536 + c * 1024 + tlo * 8 + P * 4));
            const uint4* Ap = (const uint4*)(g_h1s + ((t - 1) & 3) * 16384) + kq * 1024 + mh * 64 + lane;
            waitflag(&g_f1[t].g[kq], 16);              // exactly this warp's kt range
            gemm8x2_regB(acc, Ap, bq1, bq2);
            if (t >= 4) waitflag4(&g_f2[t - 3], 16);   // ring guard, off the front
        } else {
            const uint4* Ap1 = (const uint4*)(g_h1s + (t & 3) * 16384) + kq * 1024 + mh * 64 + lane;
            waitflag(&g_f1[t + 1].g[kq], 16);          // h1[t] (layer1 runs ahead)
            gemm8x2(acc, Ap1, Bs + kq * 512 + lane);   // W_ih1 quarter (smem B, skew window)
            const uint4* Ap2 = (const uint4*)(g_h2s + ((t - 1) & 1) * 16384) + kq * 1024 + mh * 64 + lane;
            waitflag(&g_f2[t].g[kq], 16);              // h2[t-1] — serial dep
            gemm8x2_regB(acc, Ap2, bq1, bq2);          // W_hh1 quarter (REGISTER B, no LDS)
        }
        // ship the 3 unowned (mi, nt-pair) chunks
#pragma unroll
        for (int mi = 0; mi < 2; mi++) {
#pragma unroll
            for (int p = 0; p < 2; p++) {
                if (mi == mI && p == P) continue;      // keep own chunk in regs
                int oidx = ((((mh * 2 + mi) * 2 + p) * 4 + kq) * 32 + lane) * 2;
                EX[oidx]     = make_float4(acc[mi][p * 2][0], acc[mi][p * 2][1],
                                           acc[mi][p * 2][2], acc[mi][p * 2][3]);
                EX[oidx + 1] = make_float4(acc[mi][p * 2 + 1][0], acc[mi][p * 2 + 1][1],
                                           acc[mi][p * 2 + 1][2], acc[mi][p * 2 + 1][3]);
            }
        }
        __syncthreads();
        {
            float v[8];
#pragma unroll
            for (int e = 0; e < 4; e++) { v[e] = acc[mI][P * 2][e]; v[4 + e] = acc[mI][P * 2 + 1][e]; }
#pragma unroll
            for (int src = 0; src < 4; src++) {
                if (src == kq) continue;
                int iidx = (((mtS * 2 + P) * 4 + src) * 32 + lane) * 2;
                float4 fa = EX[iidx], fb = EX[iidx + 1];
                v[0] += fa.x; v[1] += fa.y; v[2] += fa.z; v[3] += fa.w;
                v[4] += fb.x; v[5] += fb.y; v[6] += fb.z; v[7] += fb.w;
            }
            if (!layer) {
                const __half2* hx = (const __half2*)&xg;
#pragma unroll
                for (int k = 0; k < 4; k++) {
                    float2 p2 = __half22float2(hx[k]);
                    v[k * 2] += p2.x; v[k * 2 + 1] += p2.y;
                }
            } else {
#pragma unroll
                for (int k = 0; k < 8; k++) v[k] += bias8[k];
            }
            uint32_t* slab = layer ? (g_h2s + (t & 1) * 16384) : (g_h1s + (t & 3) * 16384);
            uint16_t* hp = (uint16_t*)slab;
#pragma unroll
            for (int bb = 0; bb < 2; bb++) {
                float iv = sigm(v[bb * 2]);
                float fv = sigm(v[bb * 2 + 1]);
                float gv = tanha(v[4 + bb * 2]);
                float ov = sigm(v[4 + bb * 2 + 1]);
                float cv = fmaf(fv, cst[bb], iv * gv);
                cst[bb] = cv;
                float hv = ov * tanha(cv);
                __half hh = __float2half_rn(hv);
                hp[(sbase + bb) * 2 + hpar] = __half_as_ushort(hh);
            }
        }
        __syncthreads();   // h-stores + EX reuse guard
        if (tid == 0) {
            unsigned* fp = layer ? &g_f2[t + 1].g[myGrp] : &g_f1[t + 1].g[myGrp];
            asm volatile("red.release.gpu.global.add.u32 [%0], 1;" ::"l"(fp) : "memory");
        }
    }
}

// ---------------- final projection ----------------
__global__ void out_kernel(const float* __restrict__ Wout, const float* __restrict__ bout,
                           float* __restrict__ out) {
    __shared__ float hs[512];
    int b = blockIdx.x;
    const uint32_t* slab = g_h2s + ((TT - 1) & 1) * 16384;
    for (int k = threadIdx.x; k < 512; k += 64) {
        int kt = k >> 4, ku = k & 15, mtb = b >> 4, r = b & 15;
        int laneS = (r & 7) * 4 + ((ku & 7) >> 1);
        int reg = (r >> 3) + 2 * (ku >> 3);
        uint32_t v = slab[((kt * 4 + mtb) * 32 + laneS) * 4 + reg];
        __half2 h2v = *reinterpret_cast<__half2*>(&v);
        hs[k] = (ku & 1) ? __high2float(h2v) : __low2float(h2v);
    }
    __syncthreads();
    int o = threadIdx.x;
    float acc = bout[o];
    const float* wr = Wout + o * HH;
#pragma unroll 8
    for (int k = 0; k < HH; k++) acc = fmaf(hs[k], wr[k], acc);
    out[b * 64 + o] = acc;
}

// ---------------- launch ----------------
extern "C" void kernel_launch(void* const* d_in, const int* in_sizes, int n_in,
                              void* d_out, int out_size) {
    const float* x    = (const float*)d_in[0];
    const float* Wih0 = (const float*)d_in[1];
    const float* Whh0 = (const float*)d_in[2];
    const float* bih0 = (const float*)d_in[3];
    const float* bhh0 = (const float*)d_in[4];
    const float* Wih1 = (const float*)d_in[5];
    const float* Whh1 = (const float*)d_in[6];
    const float* bih1 = (const float*)d_in[7];
    const float* bhh1 = (const float*)d_in[8];
    const float* Wout = (const float*)d_in[9];
    const float* bout = (const float*)d_in[10];
    float* out = (float*)d_out;

    cudaFuncSetAttribute(lstm_kernel, cudaFuncAttributeMaxDynamicSharedMemorySize, SMEM_BYTES);

    reset_kernel<<<64, 256>>>();
    pack_kernel<<<128, 256>>>(Whh0, Wih0, Wih1, Whh1, bih0, bhh0, bih1, bhh1);
    xpack_kernel<<<TT, 384>>>(x);
    xg0tc_kernel<<<((TT + 7) / 8) * 64, 256>>>();
    lstm_kernel<<<GRID, NT, SMEM_BYTES>>>();
    out_kernel<<<64, 64>>>(Wout, bout, out);
}